// round 15
// baseline (speedup 1.0000x reference)
#include <cuda_runtime.h>
#include <cuda_bf16.h>
#include <cstdint>

#define IMGS   128
#define EMB    256
#define NPIX   32768
#define VOCAB  4096
#define NLRING 16          // per-(lane,row) ring capacity
#define NC_MAX 64          // max candidates per pixel (4 lanes x 16)

__device__ float g_csq[VOCAB];
__device__ float g_csqh[VOCAB];
__device__ int   g_tok[NPIX];
__device__ __nv_bfloat16 g_cbh[VOCAB * EMB];
__device__ unsigned short g_cand[NPIX][NC_MAX];
__device__ int   g_cnt[NPIX];
__device__ int   g_nfb;
__device__ int   g_fblist[NPIX];
__device__ int   g_namb;
__device__ int   g_amblist[NPIX];

__device__ __forceinline__ unsigned int f2ord(float f) {
    unsigned int u = __float_as_uint(f);
    return (u & 0x80000000u) ? ~u : (u | 0x80000000u);
}
__device__ __forceinline__ uint32_t smem_u32(const void* p) {
    uint32_t a;
    asm("{ .reg .u64 t; cvta.to.shared.u64 t, %1; cvt.u32.u64 %0, t; }" : "=r"(a) : "l"(p));
    return a;
}

#define LDM4(r0, r1, r2, r3, addr)                                              \
    asm volatile("ldmatrix.sync.aligned.m8n8.x4.shared.b16 {%0,%1,%2,%3}, [%4];"\
        : "=r"(r0), "=r"(r1), "=r"(r2), "=r"(r3) : "r"(addr))

#define MMA16816(d, a0, a1, a2, a3, b0, b1)                                     \
    asm volatile("mma.sync.aligned.m16n8k16.row.col.f32.bf16.bf16.f32 "         \
        "{%0,%1,%2,%3},{%4,%5,%6,%7},{%8,%9},{%0,%1,%2,%3};"                    \
        : "+f"((d)[0]), "+f"((d)[1]), "+f"((d)[2]), "+f"((d)[3])                \
        : "r"(a0), "r"(a1), "r"(a2), "r"(a3), "r"(b0), "r"(b1))

#define CPA16(dst, src)                                                         \
    asm volatile("cp.async.cg.shared.global [%0], [%1], 16;" :: "r"(dst), "l"(src))
#define CP_COMMIT() asm volatile("cp.async.commit_group;" ::: "memory")

// ---------------------------------------------------------------------------
// prep: bf16 codebook + csq (+ counters reset). One block per codebook row.
// ---------------------------------------------------------------------------
__global__ void __launch_bounds__(256) k_prep(const float* __restrict__ cb) {
    __shared__ float red[8];
    const int r = blockIdx.x, t = threadIdx.x;
    if (r == 0 && t == 0) { g_nfb = 0; g_namb = 0; }
    float v = cb[r * 256 + t];
    g_cbh[r * 256 + t] = __float2bfloat16(v);
    float s = v * v;
    #pragma unroll
    for (int o = 16; o; o >>= 1) s += __shfl_down_sync(0xFFFFFFFFu, s, o);
    if ((t & 31) == 0) red[t >> 5] = s;
    __syncthreads();
    if (t == 0) {
        float tot = 0.f;
        #pragma unroll
        for (int i = 0; i < 8; i++) tot += red[i];
        g_csq[r] = tot; g_csqh[r] = 0.5f * tot;
    }
}

// ---------------------------------------------------------------------------
// fp32 256x256x256 GEMM: 128x128 tile, 8x8 microtile, K-chunk 16,
// double-buffered smem, ONE sync per K-iteration. Bit-identical accumulation.
// ---------------------------------------------------------------------------
template<bool XFORM>
__global__ void __launch_bounds__(256) k_gemm256(
    const float* __restrict__ W, const float* __restrict__ bias,
    const float* __restrict__ In, float* __restrict__ Out)
{
    __shared__ float As[2][16][132];
    __shared__ float Bs[2][16][128];
    const int img = blockIdx.z;
    const int m0 = blockIdx.y * 128, n0 = blockIdx.x * 128;
    const float* in = In + (size_t)img * 65536;
    float* out = Out + (size_t)img * 65536;
    const int t = threadIdx.x;
    const int ty = t >> 4, tx = t & 15;

    const int wm  = t >> 1;
    const int wk  = (t & 1) * 8;
    const int ik  = t >> 4;
    const int in4 = (t & 15) * 8;

    float acc[8][8] = {};

    {
        float4 w0 = *reinterpret_cast<const float4*>(&W[(m0 + wm) * 256 + wk]);
        float4 w1 = *reinterpret_cast<const float4*>(&W[(m0 + wm) * 256 + wk + 4]);
        float4 b0 = *reinterpret_cast<const float4*>(&in[ik * 256 + n0 + in4]);
        float4 b1 = *reinterpret_cast<const float4*>(&in[ik * 256 + n0 + in4 + 4]);
        if (XFORM) {
            b0.x = 2.f * b0.x - 1.f; b0.y = 2.f * b0.y - 1.f;
            b0.z = 2.f * b0.z - 1.f; b0.w = 2.f * b0.w - 1.f;
            b1.x = 2.f * b1.x - 1.f; b1.y = 2.f * b1.y - 1.f;
            b1.z = 2.f * b1.z - 1.f; b1.w = 2.f * b1.w - 1.f;
        }
        As[0][wk + 0][wm] = w0.x; As[0][wk + 1][wm] = w0.y;
        As[0][wk + 2][wm] = w0.z; As[0][wk + 3][wm] = w0.w;
        As[0][wk + 4][wm] = w1.x; As[0][wk + 5][wm] = w1.y;
        As[0][wk + 6][wm] = w1.z; As[0][wk + 7][wm] = w1.w;
        *reinterpret_cast<float4*>(&Bs[0][ik][in4])     = b0;
        *reinterpret_cast<float4*>(&Bs[0][ik][in4 + 4]) = b1;
    }
    __syncthreads();

    #pragma unroll 1
    for (int kt = 0; kt < 16; kt++) {
        const int s = kt & 1;
        float4 w0, w1, b0, b1;
        if (kt < 15) {
            const int k0 = (kt + 1) * 16;
            w0 = *reinterpret_cast<const float4*>(&W[(m0 + wm) * 256 + k0 + wk]);
            w1 = *reinterpret_cast<const float4*>(&W[(m0 + wm) * 256 + k0 + wk + 4]);
            b0 = *reinterpret_cast<const float4*>(&in[(k0 + ik) * 256 + n0 + in4]);
            b1 = *reinterpret_cast<const float4*>(&in[(k0 + ik) * 256 + n0 + in4 + 4]);
            if (XFORM) {
                b0.x = 2.f * b0.x - 1.f; b0.y = 2.f * b0.y - 1.f;
                b0.z = 2.f * b0.z - 1.f; b0.w = 2.f * b0.w - 1.f;
                b1.x = 2.f * b1.x - 1.f; b1.y = 2.f * b1.y - 1.f;
                b1.z = 2.f * b1.z - 1.f; b1.w = 2.f * b1.w - 1.f;
            }
        }
        #pragma unroll
        for (int k = 0; k < 16; k++) {
            float a[8], b[8];
            *reinterpret_cast<float4*>(a)     = *reinterpret_cast<float4*>(&As[s][k][ty * 8]);
            *reinterpret_cast<float4*>(a + 4) = *reinterpret_cast<float4*>(&As[s][k][ty * 8 + 4]);
            *reinterpret_cast<float4*>(b)     = *reinterpret_cast<float4*>(&Bs[s][k][tx * 8]);
            *reinterpret_cast<float4*>(b + 4) = *reinterpret_cast<float4*>(&Bs[s][k][tx * 8 + 4]);
            #pragma unroll
            for (int i = 0; i < 8; i++)
                #pragma unroll
                for (int j = 0; j < 8; j++)
                    acc[i][j] += a[i] * b[j];
        }
        if (kt < 15) {
            const int d = s ^ 1;
            As[d][wk + 0][wm] = w0.x; As[d][wk + 1][wm] = w0.y;
            As[d][wk + 2][wm] = w0.z; As[d][wk + 3][wm] = w0.w;
            As[d][wk + 4][wm] = w1.x; As[d][wk + 5][wm] = w1.y;
            As[d][wk + 6][wm] = w1.z; As[d][wk + 7][wm] = w1.w;
            *reinterpret_cast<float4*>(&Bs[d][ik][in4])     = b0;
            *reinterpret_cast<float4*>(&Bs[d][ik][in4 + 4]) = b1;
        }
        __syncthreads();
    }

    #pragma unroll
    for (int i = 0; i < 8; i++) {
        int m = m0 + ty * 8 + i;
        float bm = bias[m];
        float4 o0, o1;
        o0.x = acc[i][0] + bm; o0.y = acc[i][1] + bm;
        o0.z = acc[i][2] + bm; o0.w = acc[i][3] + bm;
        o1.x = acc[i][4] + bm; o1.y = acc[i][5] + bm;
        o1.z = acc[i][6] + bm; o1.w = acc[i][7] + bm;
        *reinterpret_cast<float4*>(&out[m * 256 + n0 + tx * 8])     = o0;
        *reinterpret_cast<float4*>(&out[m * 256 + n0 + tx * 8 + 4]) = o1;
    }
}

// ---------------------------------------------------------------------------
// bf16 mma.sync score GEMM, gated prune + GROUP-LEVEL top-2 for skip.
// Ambiguous pixels are appended to g_amblist for the compacted rescore.
// ---------------------------------------------------------------------------
#define AOFF      0
#define B0OFF     65536
#define B1OFF     81920
#define CSQOFF    98304
#define RINGOFF   98560
#define SMEM_DIST 114944
#define MARGIN    2.5e-5f
#define SKIP_GAP  2.5e-5f

__global__ void __launch_bounds__(256, 2) k_dist_mma(
    const float* __restrict__ z, float* __restrict__ tok_out)
{
    extern __shared__ char smem[];
    const uint32_t sb = smem_u32(smem);
    const int t = threadIdx.x;
    const int wid = t >> 5, lane = t & 31;
    const int n_base = blockIdx.x * 128;

    // ---- A build ----
    {
        const float* zsrc = z + (size_t)(n_base >> 8) * 65536 + (n_base & 255);
        float* scr = reinterpret_cast<float*>(smem + B0OFF);
        for (int kb = 0; kb < 8; kb++) {
            int e_l = t >> 3;
            int pg = (t & 7) * 16;
            const float4* s4 = reinterpret_cast<const float4*>(zsrc + (kb * 32 + e_l) * 256 + pg);
            float4 v0 = s4[0], v1 = s4[1], v2 = s4[2], v3 = s4[3];
            float4* d4 = reinterpret_cast<float4*>(scr + e_l * 128 + pg);
            d4[0] = v0; d4[1] = v1; d4[2] = v2; d4[3] = v3;
            __syncthreads();
            int pix = t & 127, half = t >> 7;
            #pragma unroll
            for (int jj = 0; jj < 8; jj++) {
                int el0 = (half * 8 + jj) * 2;
                float a = scr[el0 * 128 + pix], b = scr[(el0 + 1) * 128 + pix];
                uint32_t u;
                asm("cvt.rn.bf16x2.f32 %0, %1, %2;" : "=r"(u) : "f"(b), "f"(a));
                int eg = kb * 32 + el0;
                uint32_t unit = (uint32_t)(eg >> 3);
                uint32_t su = (unit & 24) | ((unit ^ (uint32_t)(pix & 7)) & 7);
                uint32_t addr = sb + AOFF + (uint32_t)pix * 512 + su * 16 + (eg & 7) * 2;
                asm volatile("st.shared.b32 [%0], %1;" :: "r"(addr), "r"(u) : "memory");
            }
            __syncthreads();
        }
    }

    const int wbase = wid * 16;
    const int arow = wbase + (lane & 7) + ((lane >> 3) & 1) * 8;
    const uint32_t aswz = (uint32_t)(arow & 7);
    const uint32_t abase = sb + AOFF + (uint32_t)arow * 512;
    const int ag2 = lane >> 4;
    const int brp = ((lane >> 4) & 1) * 8 + (lane & 7);
    const int bg1 = (lane >> 3) & 1;
    float* csq_s = reinterpret_cast<float*>(smem + CSQOFF);
    unsigned short* ringp =
        reinterpret_cast<unsigned short*>(smem + RINGOFF) + (wid * 32 + lane) * (2 * NLRING);

    float acc[8][4];
    #pragma unroll
    for (int i = 0; i < 8; i++)
        #pragma unroll
        for (int j = 0; j < 4; j++) acc[i][j] = 0.f;

    float rmx_lo = -1e30f, rmx_hi = -1e30f;
    float s1_lo = -1e30f, s2_lo = -1e30f;
    float s1_hi = -1e30f, s2_hi = -1e30f;
    int   i1_lo = 0, i1_hi = 0;
    int cl = 0, ch = 0;

    auto loadB = [&](int nt, int kc, uint32_t boff) {
        int code = t >> 2;
        const char* src = reinterpret_cast<const char*>(
            g_cbh + ((size_t)(nt * 64 + code)) * 256 + kc * 128 + (t & 3) * 32);
        uint32_t drow = sb + boff + (uint32_t)code * 256;
        uint32_t sw = (uint32_t)(code & 7);
        #pragma unroll
        for (int i = 0; i < 4; i++) {
            uint32_t u = (uint32_t)((t & 3) * 4 + i);
            uint32_t su = ((u ^ sw) & 7) | (u & 8);
            CPA16(drow + su * 16, src + i * 16);
        }
    };

    loadB(0, 0, B0OFF);
    CP_COMMIT();

    for (int c = 0; c < 128; ++c) {
        const int nt = c >> 1, kc = c & 1;
        if (c < 127) { loadB((c + 1) >> 1, (c + 1) & 1, ((c + 1) & 1) ? B1OFF : B0OFF); CP_COMMIT(); }
        if (kc == 0 && t < 64) csq_s[t] = g_csqh[nt * 64 + t];
        if (c < 127) asm volatile("cp.async.wait_group 1;" ::: "memory");
        else         asm volatile("cp.async.wait_group 0;" ::: "memory");
        __syncthreads();

        const uint32_t bbuf = sb + ((c & 1) ? B1OFF : B0OFF);
        #pragma unroll
        for (int ks = 0; ks < 8; ks++) {
            uint32_t a0, a1, a2, a3;
            {
                uint32_t unit = (uint32_t)(kc * 16 + 2 * ks + ag2);
                uint32_t su = (unit & 24) | ((unit ^ aswz) & 7);
                LDM4(a0, a1, a2, a3, abase + su * 16);
            }
            #pragma unroll
            for (int p = 0; p < 4; p++) {
                int brow = p * 16 + brp;
                uint32_t unit = (uint32_t)(2 * ks + bg1);
                uint32_t su = (unit & 8) | ((unit ^ (uint32_t)(brow & 7)) & 7);
                uint32_t b0, b1, b2, b3;
                LDM4(b0, b1, b2, b3, bbuf + (uint32_t)brow * 256 + su * 16);
                MMA16816(acc[2 * p],     a0, a1, a2, a3, b0, b1);
                MMA16816(acc[2 * p + 1], a0, a1, a2, a3, b2, b3);
            }
        }

        if (kc == 1) {
            const int vtile = nt * 64;
            #pragma unroll
            for (int q = 0; q < 4; ++q) {
                const int cbase = q * 16 + 2 * (lane & 3);
                float2 cq0 = *reinterpret_cast<const float2*>(csq_s + cbase);
                float2 cq1 = *reinterpret_cast<const float2*>(csq_s + cbase + 8);
                const int nf0 = 2 * q, nf1 = 2 * q + 1;
                // ---- low row ----
                {
                    float s0 = acc[nf0][0] - cq0.x, s1v = acc[nf0][1] - cq0.y;
                    float s2v = acc[nf1][0] - cq1.x, s3v = acc[nf1][1] - cq1.y;
                    float m01 = fmaxf(s0, s1v), m23 = fmaxf(s2v, s3v);
                    float m = fmaxf(m01, m23);
                    if (m > s1_lo) {
                        float mn01 = fminf(s0, s1v), mn23 = fminf(s2v, s3v);
                        float sec = (m01 >= m23) ? fmaxf(m23, mn01) : fmaxf(m01, mn23);
                        int gi = (m == s0) ? cbase : (m == s1v) ? (cbase + 1)
                               : (m == s2v) ? (cbase + 8) : (cbase + 9);
                        s2_lo = fmaxf(s1_lo, sec);
                        s1_lo = m;
                        i1_lo = vtile + gi;
                    } else {
                        s2_lo = fmaxf(s2_lo, m);
                    }
                    float base = fmaxf(rmx_lo, s1_lo) - MARGIN;
                    if (m > base) {
                        if (s0  > base) { if (cl < NLRING) ringp[cl] = (unsigned short)(vtile + cbase);     cl++; }
                        if (s1v > base) { if (cl < NLRING) ringp[cl] = (unsigned short)(vtile + cbase + 1); cl++; }
                        if (s2v > base) { if (cl < NLRING) ringp[cl] = (unsigned short)(vtile + cbase + 8); cl++; }
                        if (s3v > base) { if (cl < NLRING) ringp[cl] = (unsigned short)(vtile + cbase + 9); cl++; }
                    }
                }
                // ---- high row ----
                {
                    float s0 = acc[nf0][2] - cq0.x, s1v = acc[nf0][3] - cq0.y;
                    float s2v = acc[nf1][2] - cq1.x, s3v = acc[nf1][3] - cq1.y;
                    float m01 = fmaxf(s0, s1v), m23 = fmaxf(s2v, s3v);
                    float m = fmaxf(m01, m23);
                    if (m > s1_hi) {
                        float mn01 = fminf(s0, s1v), mn23 = fminf(s2v, s3v);
                        float sec = (m01 >= m23) ? fmaxf(m23, mn01) : fmaxf(m01, mn23);
                        int gi = (m == s0) ? cbase : (m == s1v) ? (cbase + 1)
                               : (m == s2v) ? (cbase + 8) : (cbase + 9);
                        s2_hi = fmaxf(s1_hi, sec);
                        s1_hi = m;
                        i1_hi = vtile + gi;
                    } else {
                        s2_hi = fmaxf(s2_hi, m);
                    }
                    float base = fmaxf(rmx_hi, s1_hi) - MARGIN;
                    if (m > base) {
                        if (s0  > base) { if (ch < NLRING) ringp[NLRING + ch] = (unsigned short)(vtile + cbase);     ch++; }
                        if (s1v > base) { if (ch < NLRING) ringp[NLRING + ch] = (unsigned short)(vtile + cbase + 1); ch++; }
                        if (s2v > base) { if (ch < NLRING) ringp[NLRING + ch] = (unsigned short)(vtile + cbase + 8); ch++; }
                        if (s3v > base) { if (ch < NLRING) ringp[NLRING + ch] = (unsigned short)(vtile + cbase + 9); ch++; }
                    }
                }
            }
            {
                float q0 = fmaxf(s1_lo, __shfl_xor_sync(0xFFFFFFFFu, s1_lo, 1));
                rmx_lo = fmaxf(q0, __shfl_xor_sync(0xFFFFFFFFu, q0, 2));
                float q1 = fmaxf(s1_hi, __shfl_xor_sync(0xFFFFFFFFu, s1_hi, 1));
                rmx_hi = fmaxf(q1, __shfl_xor_sync(0xFFFFFFFFu, q1, 2));
            }
            #pragma unroll
            for (int i = 0; i < 8; i++)
                #pragma unroll
                for (int j = 0; j < 4; j++) acc[i][j] = 0.f;
        }
        __syncthreads();
    }

    // ---- per-pixel merge ----
    const unsigned qb = lane & ~3u;
    const int liq = lane & 3;
    #pragma unroll
    for (int rowsel = 0; rowsel < 2; ++rowsel) {
        int mycnt = rowsel ? ch : cl;
        float s1 = rowsel ? s1_hi : s1_lo;
        float s2 = rowsel ? s2_hi : s2_lo;
        int   i1 = rowsel ? i1_hi : i1_lo;
        #pragma unroll
        for (int off = 1; off <= 2; off <<= 1) {
            float os1 = __shfl_xor_sync(0xFFFFFFFFu, s1, off);
            float os2 = __shfl_xor_sync(0xFFFFFFFFu, s2, off);
            int   oi1 = __shfl_xor_sync(0xFFFFFFFFu, i1, off);
            if (os1 > s1) { s2 = fmaxf(fmaxf(s1, os2), s2); s1 = os1; i1 = oi1; }
            else          { s2 = fmaxf(fmaxf(os1, os2), s2); }
        }
        bool skip = (s1 - s2) > SKIP_GAP;

        int l0 = __shfl_sync(0xFFFFFFFFu, mycnt, qb + 0);
        int l1 = __shfl_sync(0xFFFFFFFFu, mycnt, qb + 1);
        int l2 = __shfl_sync(0xFFFFFFFFu, mycnt, qb + 2);
        int l3 = __shfl_sync(0xFFFFFFFFu, mycnt, qb + 3);
        int m0 = min(l0, NLRING), m1 = min(l1, NLRING),
            m2 = min(l2, NLRING), m3 = min(l3, NLRING);
        int tot = m0 + m1 + m2 + m3;
        bool ovf = (l0 > NLRING) | (l1 > NLRING) | (l2 > NLRING) | (l3 > NLRING);
        int pre = (liq > 0 ? m0 : 0) + (liq > 1 ? m1 : 0) + (liq > 2 ? m2 : 0);
        int pix = n_base + wbase + (lane >> 2) + rowsel * 8;
        if (liq == 0) {
            if (skip) {
                g_tok[pix] = i1;
                tok_out[pix] = (float)i1;
            } else {
                g_cnt[pix] = ovf ? 1000 : tot;
                int idx = atomicAdd(&g_namb, 1);
                g_amblist[idx] = pix;
            }
        }
        if (!skip) {
            int myc = min(mycnt, NLRING);
            const unsigned short* rp = ringp + rowsel * NLRING;
            for (int i = 0; i < myc; ++i) g_cand[pix][pre + i] = rp[i];
        }
    }
}

// ---------------------------------------------------------------------------
// Rescore v5: compacted list, persistent warp-per-pixel, coalesced cb rows.
// ---------------------------------------------------------------------------
__global__ void __launch_bounds__(256) k_rescore(
    const float* __restrict__ cb, const float* __restrict__ z,
    float* __restrict__ tok_out)
{
    const int wslot = blockIdx.x * 8 + (threadIdx.x >> 5);
    const int lane = threadIdx.x & 31;
    const int n = g_namb;

    for (int i = wslot; i < n; i += 1024) {
        const int pix = g_amblist[i];
        const int cnt = g_cnt[pix];
        if (cnt > NC_MAX) {
            if (lane == 0) { int idx = atomicAdd(&g_nfb, 1); g_fblist[idx] = pix; }
            continue;
        }
        // load z row: lane owns e = lane*8 .. lane*8+7
        const float* zp = z + (size_t)(pix >> 8) * 65536 + (pix & 255);
        float zr[8];
        #pragma unroll
        for (int j = 0; j < 8; j++) zr[j] = zp[(lane * 8 + j) * 256];
        // zsq: per-lane sequential partial + xor tree
        float zq2 = zr[0] * zr[0];
        #pragma unroll
        for (int j = 1; j < 8; j++) zq2 = fmaf(zr[j], zr[j], zq2);
        #pragma unroll
        for (int o = 16; o; o >>= 1) zq2 += __shfl_xor_sync(0xFFFFFFFFu, zq2, o);

        unsigned long long best = ~0ull;
        for (int ci = 0; ci < cnt; ci += 2) {
            int v0 = g_cand[pix][ci];
            int v1 = (ci + 1 < cnt) ? g_cand[pix][ci + 1] : v0;
            const float4* cp0 = reinterpret_cast<const float4*>(cb + (size_t)v0 * 256 + lane * 8);
            const float4* cp1 = reinterpret_cast<const float4*>(cb + (size_t)v1 * 256 + lane * 8);
            float4 c00 = cp0[0], c01 = cp0[1];
            float4 c10 = cp1[0], c11 = cp1[1];
            float p0 = zr[0] * c00.x, p1 = zr[0] * c10.x;
            p0 = fmaf(zr[1], c00.y, p0); p1 = fmaf(zr[1], c10.y, p1);
            p0 = fmaf(zr[2], c00.z, p0); p1 = fmaf(zr[2], c10.z, p1);
            p0 = fmaf(zr[3], c00.w, p0); p1 = fmaf(zr[3], c10.w, p1);
            p0 = fmaf(zr[4], c01.x, p0); p1 = fmaf(zr[4], c11.x, p1);
            p0 = fmaf(zr[5], c01.y, p0); p1 = fmaf(zr[5], c11.y, p1);
            p0 = fmaf(zr[6], c01.z, p0); p1 = fmaf(zr[6], c11.z, p1);
            p0 = fmaf(zr[7], c01.w, p0); p1 = fmaf(zr[7], c11.w, p1);
            #pragma unroll
            for (int o = 16; o; o >>= 1) {
                p0 += __shfl_xor_sync(0xFFFFFFFFu, p0, o);
                p1 += __shfl_xor_sync(0xFFFFFFFFu, p1, o);
            }
            float d0 = (zq2 + g_csq[v0]) - 2.0f * p0;
            unsigned long long k0 = ((unsigned long long)f2ord(d0) << 32) | (unsigned int)v0;
            if (k0 < best) best = k0;
            if (ci + 1 < cnt) {
                float d1 = (zq2 + g_csq[v1]) - 2.0f * p1;
                unsigned long long k1 = ((unsigned long long)f2ord(d1) << 32) | (unsigned int)v1;
                if (k1 < best) best = k1;
            }
        }
        if (lane == 0) {
            int tok = (int)(best & 0xFFFFFFFFull);
            g_tok[pix] = tok;
            tok_out[pix] = (float)tok;
        }
    }
}

// ---------------------------------------------------------------------------
// Fallback: block-per-pixel, warp-per-code (coalesced row reads).
// ---------------------------------------------------------------------------
__global__ void __launch_bounds__(256) k_fallback(
    const float* __restrict__ cb, const float* __restrict__ z,
    float* __restrict__ tok_out)
{
    __shared__ float zr[256];
    __shared__ float zsq_sh;
    __shared__ unsigned long long wmin[8];
    const int t = threadIdx.x;
    const int wid = t >> 5, lane = t & 31;
    const int n = g_nfb;

    for (int i = blockIdx.x; i < n; i += gridDim.x) {
        const int pix = g_fblist[i];
        const float* zsrc = z + (size_t)(pix >> 8) * 65536 + (pix & 255);
        zr[t] = zsrc[t * 256];
        __syncthreads();
        if (t == 0) {
            float s = 0.f;
            #pragma unroll 8
            for (int e = 0; e < 256; e++) { float v = zr[e]; s = fmaf(v, v, s); }
            zsq_sh = s;
        }
        __syncthreads();
        const float zq2 = zsq_sh;
        const float4 z0 = *reinterpret_cast<const float4*>(zr + lane * 8);
        const float4 z1 = *reinterpret_cast<const float4*>(zr + lane * 8 + 4);
        unsigned long long best = ~0ull;

        for (int v = wid * 512; v < wid * 512 + 512; v += 2) {
            const float4* c0p = reinterpret_cast<const float4*>(cb + (size_t)v * 256 + lane * 8);
            const float4* c1p = reinterpret_cast<const float4*>(cb + (size_t)(v + 1) * 256 + lane * 8);
            float4 c00 = c0p[0], c01 = c0p[1];
            float4 c10 = c1p[0], c11 = c1p[1];
            float p0 = z0.x * c00.x, p1 = z0.x * c10.x;
            p0 = fmaf(z0.y, c00.y, p0); p1 = fmaf(z0.y, c10.y, p1);
            p0 = fmaf(z0.z, c00.z, p0); p1 = fmaf(z0.z, c10.z, p1);
            p0 = fmaf(z0.w, c00.w, p0); p1 = fmaf(z0.w, c10.w, p1);
            p0 = fmaf(z1.x, c01.x, p0); p1 = fmaf(z1.x, c11.x, p1);
            p0 = fmaf(z1.y, c01.y, p0); p1 = fmaf(z1.y, c11.y, p1);
            p0 = fmaf(z1.z, c01.z, p0); p1 = fmaf(z1.z, c11.z, p1);
            p0 = fmaf(z1.w, c01.w, p0); p1 = fmaf(z1.w, c11.w, p1);
            #pragma unroll
            for (int o = 16; o; o >>= 1) {
                p0 += __shfl_xor_sync(0xFFFFFFFFu, p0, o);
                p1 += __shfl_xor_sync(0xFFFFFFFFu, p1, o);
            }
            float d0 = (zq2 + g_csq[v])     - 2.0f * p0;
            float d1 = (zq2 + g_csq[v + 1]) - 2.0f * p1;
            unsigned long long k0 = ((unsigned long long)f2ord(d0) << 32) | (unsigned int)v;
            unsigned long long k1 = ((unsigned long long)f2ord(d1) << 32) | (unsigned int)(v + 1);
            if (k0 < best) best = k0;
            if (k1 < best) best = k1;
        }
        if (lane == 0) wmin[wid] = best;
        __syncthreads();
        if (t == 0) {
            unsigned long long b = wmin[0];
            #pragma unroll
            for (int k = 1; k < 8; k++) if (wmin[k] < b) b = wmin[k];
            int tok = (int)(b & 0xFFFFFFFFull);
            g_tok[pix] = tok;
            tok_out[pix] = (float)tok;
        }
        __syncthreads();
    }
}

__global__ void k_zq(const float* __restrict__ cb, float* __restrict__ zq) {
    unsigned int g = blockIdx.x * 256 + threadIdx.x;
    int hw = g & 255, e = (g >> 8) & 255, img = g >> 16;
    zq[g] = cb[(size_t)g_tok[img * 256 + hw] * 256 + e];
}

// ---------------------------------------------------------------------------
extern "C" void kernel_launch(void* const* d_in, const int* in_sizes, int n_in,
                              void* d_out, int out_size) {
    const float* x      = (const float*)d_in[0];
    const float* cb     = (const float*)d_in[1];
    const float* pre_w  = (const float*)d_in[2];
    const float* pre_b  = (const float*)d_in[3];
    const float* post_w = (const float*)d_in[4];
    const float* post_b = (const float*)d_in[5];

    float* out   = (float*)d_out;
    float* zbuf  = out;
    float* zq    = out + 8388608;
    float* recon = out + 16777216;
    float* toks  = out + 25165824;

    static bool attr_done = false;
    if (!attr_done) {
        cudaFuncSetAttribute(k_dist_mma, cudaFuncAttributeMaxDynamicSharedMemorySize, SMEM_DIST);
        attr_done = true;
    }

    k_prep<<<VOCAB, 256>>>(cb);                                        // 1
    k_gemm256<true><<<dim3(2, 2, IMGS), 256>>>(pre_w, pre_b, x, zbuf); // 2
    k_dist_mma<<<NPIX / 128, 256, SMEM_DIST>>>(zbuf, toks);            // 3
    k_rescore<<<128, 256>>>(cb, zbuf, toks);                           // 4 (profiled slot)
    k_fallback<<<256, 256>>>(cb, zbuf, toks);                          // 5
    k_zq<<<8388608 / 256, 256>>>(cb, zq);                              // 6
    k_gemm256<false><<<dim3(2, 2, IMGS), 256>>>(post_w, post_b, zq, recon); // 7
}

// round 16
// speedup vs baseline: 1.1320x; 1.1320x over previous
#include <cuda_runtime.h>
#include <cuda_bf16.h>
#include <cstdint>

#define IMGS   128
#define EMB    256
#define NPIX   32768
#define VOCAB  4096
#define NLRING 16          // per-(lane,row) ring capacity
#define NC_MAX 64          // max candidates per pixel (4 lanes x 16)

__device__ float g_csq[VOCAB];
__device__ float g_csqh[VOCAB];
__device__ int   g_tok[NPIX];
__device__ __nv_bfloat16 g_cbh[VOCAB * EMB];
__device__ unsigned short g_cand[NPIX][NC_MAX];
__device__ int   g_cnt[NPIX];
__device__ int   g_nfb;
__device__ int   g_fblist[NPIX];
__device__ float g_P[EMB * VOCAB];    // P[m][v] = sum_e post_w[m][e]*cb[v][e]

__device__ __forceinline__ unsigned int f2ord(float f) {
    unsigned int u = __float_as_uint(f);
    return (u & 0x80000000u) ? ~u : (u | 0x80000000u);
}
__device__ __forceinline__ uint32_t smem_u32(const void* p) {
    uint32_t a;
    asm("{ .reg .u64 t; cvta.to.shared.u64 t, %1; cvt.u32.u64 %0, t; }" : "=r"(a) : "l"(p));
    return a;
}

#define LDM4(r0, r1, r2, r3, addr)                                              \
    asm volatile("ldmatrix.sync.aligned.m8n8.x4.shared.b16 {%0,%1,%2,%3}, [%4];"\
        : "=r"(r0), "=r"(r1), "=r"(r2), "=r"(r3) : "r"(addr))

#define MMA16816(d, a0, a1, a2, a3, b0, b1)                                     \
    asm volatile("mma.sync.aligned.m16n8k16.row.col.f32.bf16.bf16.f32 "         \
        "{%0,%1,%2,%3},{%4,%5,%6,%7},{%8,%9},{%0,%1,%2,%3};"                    \
        : "+f"((d)[0]), "+f"((d)[1]), "+f"((d)[2]), "+f"((d)[3])                \
        : "r"(a0), "r"(a1), "r"(a2), "r"(a3), "r"(b0), "r"(b1))

#define CPA16(dst, src)                                                         \
    asm volatile("cp.async.cg.shared.global [%0], [%1], 16;" :: "r"(dst), "l"(src))
#define CP_COMMIT() asm volatile("cp.async.commit_group;" ::: "memory")

// ---------------------------------------------------------------------------
// prep: bf16 codebook + csq (+ nfb reset). One block per codebook row.
// ---------------------------------------------------------------------------
__global__ void __launch_bounds__(256) k_prep(const float* __restrict__ cb) {
    __shared__ float red[8];
    const int r = blockIdx.x, t = threadIdx.x;
    if (r == 0 && t == 0) g_nfb = 0;
    float v = cb[r * 256 + t];
    g_cbh[r * 256 + t] = __float2bfloat16(v);
    float s = v * v;
    #pragma unroll
    for (int o = 16; o; o >>= 1) s += __shfl_down_sync(0xFFFFFFFFu, s, o);
    if ((t & 31) == 0) red[t >> 5] = s;
    __syncthreads();
    if (t == 0) {
        float tot = 0.f;
        #pragma unroll
        for (int i = 0; i < 8; i++) tot += red[i];
        g_csq[r] = tot; g_csqh[r] = 0.5f * tot;
    }
}

// ---------------------------------------------------------------------------
// P = post_w @ cb^T : NT fp32 GEMM, 128x128 tile, 8x8 micro, K-chunk 8.
// P[m][v] accumulated ascending-e (matches prior gemm rounding character).
// ---------------------------------------------------------------------------
__global__ void __launch_bounds__(256) k_pgemm(
    const float* __restrict__ W, const float* __restrict__ cb)
{
    __shared__ float Ws[8][132];   // [e][m]
    __shared__ float Cs[8][132];   // [e][v]
    const int m0 = blockIdx.y * 128, v0 = blockIdx.x * 128;
    const int t = threadIdx.x;
    const int ty = t >> 4, tx = t & 15;

    float acc[8][8] = {};

    for (int e0 = 0; e0 < 256; e0 += 8) {
        {
            int m = t >> 1, e4 = (t & 1) * 4;
            float4 w4 = *reinterpret_cast<const float4*>(&W[(m0 + m) * 256 + e0 + e4]);
            Ws[e4 + 0][m] = w4.x; Ws[e4 + 1][m] = w4.y;
            Ws[e4 + 2][m] = w4.z; Ws[e4 + 3][m] = w4.w;
        }
        {
            int v = t >> 1, e4 = (t & 1) * 4;
            float4 c4 = *reinterpret_cast<const float4*>(&cb[(v0 + v) * 256 + e0 + e4]);
            Cs[e4 + 0][v] = c4.x; Cs[e4 + 1][v] = c4.y;
            Cs[e4 + 2][v] = c4.z; Cs[e4 + 3][v] = c4.w;
        }
        __syncthreads();
        #pragma unroll
        for (int k = 0; k < 8; k++) {
            float a[8], b[8];
            *reinterpret_cast<float4*>(a)     = *reinterpret_cast<float4*>(&Ws[k][ty * 8]);
            *reinterpret_cast<float4*>(a + 4) = *reinterpret_cast<float4*>(&Ws[k][ty * 8 + 4]);
            *reinterpret_cast<float4*>(b)     = *reinterpret_cast<float4*>(&Cs[k][tx * 8]);
            *reinterpret_cast<float4*>(b + 4) = *reinterpret_cast<float4*>(&Cs[k][tx * 8 + 4]);
            #pragma unroll
            for (int i = 0; i < 8; i++)
                #pragma unroll
                for (int j = 0; j < 8; j++)
                    acc[i][j] += a[i] * b[j];
        }
        __syncthreads();
    }

    #pragma unroll
    for (int i = 0; i < 8; i++) {
        float* dst = g_P + (size_t)(m0 + ty * 8 + i) * 4096 + v0 + tx * 8;
        *reinterpret_cast<float4*>(dst)     = *reinterpret_cast<float4*>(&acc[i][0]);
        *reinterpret_cast<float4*>(dst + 4) = *reinterpret_cast<float4*>(&acc[i][4]);
    }
}

// ---------------------------------------------------------------------------
// fp32 256x256x256 GEMM (pre): 128x128 tile, K-chunk 16, double-buffered.
// ---------------------------------------------------------------------------
template<bool XFORM>
__global__ void __launch_bounds__(256) k_gemm256(
    const float* __restrict__ W, const float* __restrict__ bias,
    const float* __restrict__ In, float* __restrict__ Out)
{
    __shared__ float As[2][16][132];
    __shared__ float Bs[2][16][128];
    const int img = blockIdx.z;
    const int m0 = blockIdx.y * 128, n0 = blockIdx.x * 128;
    const float* in = In + (size_t)img * 65536;
    float* out = Out + (size_t)img * 65536;
    const int t = threadIdx.x;
    const int ty = t >> 4, tx = t & 15;

    const int wm  = t >> 1;
    const int wk  = (t & 1) * 8;
    const int ik  = t >> 4;
    const int in4 = (t & 15) * 8;

    float acc[8][8] = {};

    {
        float4 w0 = *reinterpret_cast<const float4*>(&W[(m0 + wm) * 256 + wk]);
        float4 w1 = *reinterpret_cast<const float4*>(&W[(m0 + wm) * 256 + wk + 4]);
        float4 b0 = *reinterpret_cast<const float4*>(&in[ik * 256 + n0 + in4]);
        float4 b1 = *reinterpret_cast<const float4*>(&in[ik * 256 + n0 + in4 + 4]);
        if (XFORM) {
            b0.x = 2.f * b0.x - 1.f; b0.y = 2.f * b0.y - 1.f;
            b0.z = 2.f * b0.z - 1.f; b0.w = 2.f * b0.w - 1.f;
            b1.x = 2.f * b1.x - 1.f; b1.y = 2.f * b1.y - 1.f;
            b1.z = 2.f * b1.z - 1.f; b1.w = 2.f * b1.w - 1.f;
        }
        As[0][wk + 0][wm] = w0.x; As[0][wk + 1][wm] = w0.y;
        As[0][wk + 2][wm] = w0.z; As[0][wk + 3][wm] = w0.w;
        As[0][wk + 4][wm] = w1.x; As[0][wk + 5][wm] = w1.y;
        As[0][wk + 6][wm] = w1.z; As[0][wk + 7][wm] = w1.w;
        *reinterpret_cast<float4*>(&Bs[0][ik][in4])     = b0;
        *reinterpret_cast<float4*>(&Bs[0][ik][in4 + 4]) = b1;
    }
    __syncthreads();

    #pragma unroll 1
    for (int kt = 0; kt < 16; kt++) {
        const int s = kt & 1;
        float4 w0, w1, b0, b1;
        if (kt < 15) {
            const int k0 = (kt + 1) * 16;
            w0 = *reinterpret_cast<const float4*>(&W[(m0 + wm) * 256 + k0 + wk]);
            w1 = *reinterpret_cast<const float4*>(&W[(m0 + wm) * 256 + k0 + wk + 4]);
            b0 = *reinterpret_cast<const float4*>(&in[(k0 + ik) * 256 + n0 + in4]);
            b1 = *reinterpret_cast<const float4*>(&in[(k0 + ik) * 256 + n0 + in4 + 4]);
            if (XFORM) {
                b0.x = 2.f * b0.x - 1.f; b0.y = 2.f * b0.y - 1.f;
                b0.z = 2.f * b0.z - 1.f; b0.w = 2.f * b0.w - 1.f;
                b1.x = 2.f * b1.x - 1.f; b1.y = 2.f * b1.y - 1.f;
                b1.z = 2.f * b1.z - 1.f; b1.w = 2.f * b1.w - 1.f;
            }
        }
        #pragma unroll
        for (int k = 0; k < 16; k++) {
            float a[8], b[8];
            *reinterpret_cast<float4*>(a)     = *reinterpret_cast<float4*>(&As[s][k][ty * 8]);
            *reinterpret_cast<float4*>(a + 4) = *reinterpret_cast<float4*>(&As[s][k][ty * 8 + 4]);
            *reinterpret_cast<float4*>(b)     = *reinterpret_cast<float4*>(&Bs[s][k][tx * 8]);
            *reinterpret_cast<float4*>(b + 4) = *reinterpret_cast<float4*>(&Bs[s][k][tx * 8 + 4]);
            #pragma unroll
            for (int i = 0; i < 8; i++)
                #pragma unroll
                for (int j = 0; j < 8; j++)
                    acc[i][j] += a[i] * b[j];
        }
        if (kt < 15) {
            const int d = s ^ 1;
            As[d][wk + 0][wm] = w0.x; As[d][wk + 1][wm] = w0.y;
            As[d][wk + 2][wm] = w0.z; As[d][wk + 3][wm] = w0.w;
            As[d][wk + 4][wm] = w1.x; As[d][wk + 5][wm] = w1.y;
            As[d][wk + 6][wm] = w1.z; As[d][wk + 7][wm] = w1.w;
            *reinterpret_cast<float4*>(&Bs[d][ik][in4])     = b0;
            *reinterpret_cast<float4*>(&Bs[d][ik][in4 + 4]) = b1;
        }
        __syncthreads();
    }

    #pragma unroll
    for (int i = 0; i < 8; i++) {
        int m = m0 + ty * 8 + i;
        float bm = bias[m];
        float4 o0, o1;
        o0.x = acc[i][0] + bm; o0.y = acc[i][1] + bm;
        o0.z = acc[i][2] + bm; o0.w = acc[i][3] + bm;
        o1.x = acc[i][4] + bm; o1.y = acc[i][5] + bm;
        o1.z = acc[i][6] + bm; o1.w = acc[i][7] + bm;
        *reinterpret_cast<float4*>(&out[m * 256 + n0 + tx * 8])     = o0;
        *reinterpret_cast<float4*>(&out[m * 256 + n0 + tx * 8 + 4]) = o1;
    }
}

// ---------------------------------------------------------------------------
// bf16 mma.sync score GEMM, gated prune + GROUP-LEVEL top-2 for skip (R14).
// ---------------------------------------------------------------------------
#define AOFF      0
#define B0OFF     65536
#define B1OFF     81920
#define CSQOFF    98304
#define RINGOFF   98560
#define SMEM_DIST 114944
#define MARGIN    2.5e-5f
#define SKIP_GAP  2.5e-5f

__global__ void __launch_bounds__(256, 2) k_dist_mma(
    const float* __restrict__ z, float* __restrict__ tok_out)
{
    extern __shared__ char smem[];
    const uint32_t sb = smem_u32(smem);
    const int t = threadIdx.x;
    const int wid = t >> 5, lane = t & 31;
    const int n_base = blockIdx.x * 128;

    {
        const float* zsrc = z + (size_t)(n_base >> 8) * 65536 + (n_base & 255);
        float* scr = reinterpret_cast<float*>(smem + B0OFF);
        for (int kb = 0; kb < 8; kb++) {
            int e_l = t >> 3;
            int pg = (t & 7) * 16;
            const float4* s4 = reinterpret_cast<const float4*>(zsrc + (kb * 32 + e_l) * 256 + pg);
            float4 v0 = s4[0], v1 = s4[1], v2 = s4[2], v3 = s4[3];
            float4* d4 = reinterpret_cast<float4*>(scr + e_l * 128 + pg);
            d4[0] = v0; d4[1] = v1; d4[2] = v2; d4[3] = v3;
            __syncthreads();
            int pix = t & 127, half = t >> 7;
            #pragma unroll
            for (int jj = 0; jj < 8; jj++) {
                int el0 = (half * 8 + jj) * 2;
                float a = scr[el0 * 128 + pix], b = scr[(el0 + 1) * 128 + pix];
                uint32_t u;
                asm("cvt.rn.bf16x2.f32 %0, %1, %2;" : "=r"(u) : "f"(b), "f"(a));
                int eg = kb * 32 + el0;
                uint32_t unit = (uint32_t)(eg >> 3);
                uint32_t su = (unit & 24) | ((unit ^ (uint32_t)(pix & 7)) & 7);
                uint32_t addr = sb + AOFF + (uint32_t)pix * 512 + su * 16 + (eg & 7) * 2;
                asm volatile("st.shared.b32 [%0], %1;" :: "r"(addr), "r"(u) : "memory");
            }
            __syncthreads();
        }
    }

    const int wbase = wid * 16;
    const int arow = wbase + (lane & 7) + ((lane >> 3) & 1) * 8;
    const uint32_t aswz = (uint32_t)(arow & 7);
    const uint32_t abase = sb + AOFF + (uint32_t)arow * 512;
    const int ag2 = lane >> 4;
    const int brp = ((lane >> 4) & 1) * 8 + (lane & 7);
    const int bg1 = (lane >> 3) & 1;
    float* csq_s = reinterpret_cast<float*>(smem + CSQOFF);
    unsigned short* ringp =
        reinterpret_cast<unsigned short*>(smem + RINGOFF) + (wid * 32 + lane) * (2 * NLRING);

    float acc[8][4];
    #pragma unroll
    for (int i = 0; i < 8; i++)
        #pragma unroll
        for (int j = 0; j < 4; j++) acc[i][j] = 0.f;

    float rmx_lo = -1e30f, rmx_hi = -1e30f;
    float s1_lo = -1e30f, s2_lo = -1e30f;
    float s1_hi = -1e30f, s2_hi = -1e30f;
    int   i1_lo = 0, i1_hi = 0;
    int cl = 0, ch = 0;

    auto loadB = [&](int nt, int kc, uint32_t boff) {
        int code = t >> 2;
        const char* src = reinterpret_cast<const char*>(
            g_cbh + ((size_t)(nt * 64 + code)) * 256 + kc * 128 + (t & 3) * 32);
        uint32_t drow = sb + boff + (uint32_t)code * 256;
        uint32_t sw = (uint32_t)(code & 7);
        #pragma unroll
        for (int i = 0; i < 4; i++) {
            uint32_t u = (uint32_t)((t & 3) * 4 + i);
            uint32_t su = ((u ^ sw) & 7) | (u & 8);
            CPA16(drow + su * 16, src + i * 16);
        }
    };

    loadB(0, 0, B0OFF);
    CP_COMMIT();

    for (int c = 0; c < 128; ++c) {
        const int nt = c >> 1, kc = c & 1;
        if (c < 127) { loadB((c + 1) >> 1, (c + 1) & 1, ((c + 1) & 1) ? B1OFF : B0OFF); CP_COMMIT(); }
        if (kc == 0 && t < 64) csq_s[t] = g_csqh[nt * 64 + t];
        if (c < 127) asm volatile("cp.async.wait_group 1;" ::: "memory");
        else         asm volatile("cp.async.wait_group 0;" ::: "memory");
        __syncthreads();

        const uint32_t bbuf = sb + ((c & 1) ? B1OFF : B0OFF);
        #pragma unroll
        for (int ks = 0; ks < 8; ks++) {
            uint32_t a0, a1, a2, a3;
            {
                uint32_t unit = (uint32_t)(kc * 16 + 2 * ks + ag2);
                uint32_t su = (unit & 24) | ((unit ^ aswz) & 7);
                LDM4(a0, a1, a2, a3, abase + su * 16);
            }
            #pragma unroll
            for (int p = 0; p < 4; p++) {
                int brow = p * 16 + brp;
                uint32_t unit = (uint32_t)(2 * ks + bg1);
                uint32_t su = (unit & 8) | ((unit ^ (uint32_t)(brow & 7)) & 7);
                uint32_t b0, b1, b2, b3;
                LDM4(b0, b1, b2, b3, bbuf + (uint32_t)brow * 256 + su * 16);
                MMA16816(acc[2 * p],     a0, a1, a2, a3, b0, b1);
                MMA16816(acc[2 * p + 1], a0, a1, a2, a3, b2, b3);
            }
        }

        if (kc == 1) {
            const int vtile = nt * 64;
            #pragma unroll
            for (int q = 0; q < 4; ++q) {
                const int cbase = q * 16 + 2 * (lane & 3);
                float2 cq0 = *reinterpret_cast<const float2*>(csq_s + cbase);
                float2 cq1 = *reinterpret_cast<const float2*>(csq_s + cbase + 8);
                const int nf0 = 2 * q, nf1 = 2 * q + 1;
                {
                    float s0 = acc[nf0][0] - cq0.x, s1v = acc[nf0][1] - cq0.y;
                    float s2v = acc[nf1][0] - cq1.x, s3v = acc[nf1][1] - cq1.y;
                    float m01 = fmaxf(s0, s1v), m23 = fmaxf(s2v, s3v);
                    float m = fmaxf(m01, m23);
                    if (m > s1_lo) {
                        float mn01 = fminf(s0, s1v), mn23 = fminf(s2v, s3v);
                        float sec = (m01 >= m23) ? fmaxf(m23, mn01) : fmaxf(m01, mn23);
                        int gi = (m == s0) ? cbase : (m == s1v) ? (cbase + 1)
                               : (m == s2v) ? (cbase + 8) : (cbase + 9);
                        s2_lo = fmaxf(s1_lo, sec);
                        s1_lo = m;
                        i1_lo = vtile + gi;
                    } else {
                        s2_lo = fmaxf(s2_lo, m);
                    }
                    float base = fmaxf(rmx_lo, s1_lo) - MARGIN;
                    if (m > base) {
                        if (s0  > base) { if (cl < NLRING) ringp[cl] = (unsigned short)(vtile + cbase);     cl++; }
                        if (s1v > base) { if (cl < NLRING) ringp[cl] = (unsigned short)(vtile + cbase + 1); cl++; }
                        if (s2v > base) { if (cl < NLRING) ringp[cl] = (unsigned short)(vtile + cbase + 8); cl++; }
                        if (s3v > base) { if (cl < NLRING) ringp[cl] = (unsigned short)(vtile + cbase + 9); cl++; }
                    }
                }
                {
                    float s0 = acc[nf0][2] - cq0.x, s1v = acc[nf0][3] - cq0.y;
                    float s2v = acc[nf1][2] - cq1.x, s3v = acc[nf1][3] - cq1.y;
                    float m01 = fmaxf(s0, s1v), m23 = fmaxf(s2v, s3v);
                    float m = fmaxf(m01, m23);
                    if (m > s1_hi) {
                        float mn01 = fminf(s0, s1v), mn23 = fminf(s2v, s3v);
                        float sec = (m01 >= m23) ? fmaxf(m23, mn01) : fmaxf(m01, mn23);
                        int gi = (m == s0) ? cbase : (m == s1v) ? (cbase + 1)
                               : (m == s2v) ? (cbase + 8) : (cbase + 9);
                        s2_hi = fmaxf(s1_hi, sec);
                        s1_hi = m;
                        i1_hi = vtile + gi;
                    } else {
                        s2_hi = fmaxf(s2_hi, m);
                    }
                    float base = fmaxf(rmx_hi, s1_hi) - MARGIN;
                    if (m > base) {
                        if (s0  > base) { if (ch < NLRING) ringp[NLRING + ch] = (unsigned short)(vtile + cbase);     ch++; }
                        if (s1v > base) { if (ch < NLRING) ringp[NLRING + ch] = (unsigned short)(vtile + cbase + 1); ch++; }
                        if (s2v > base) { if (ch < NLRING) ringp[NLRING + ch] = (unsigned short)(vtile + cbase + 8); ch++; }
                        if (s3v > base) { if (ch < NLRING) ringp[NLRING + ch] = (unsigned short)(vtile + cbase + 9); ch++; }
                    }
                }
            }
            {
                float q0 = fmaxf(s1_lo, __shfl_xor_sync(0xFFFFFFFFu, s1_lo, 1));
                rmx_lo = fmaxf(q0, __shfl_xor_sync(0xFFFFFFFFu, q0, 2));
                float q1 = fmaxf(s1_hi, __shfl_xor_sync(0xFFFFFFFFu, s1_hi, 1));
                rmx_hi = fmaxf(q1, __shfl_xor_sync(0xFFFFFFFFu, q1, 2));
            }
            #pragma unroll
            for (int i = 0; i < 8; i++)
                #pragma unroll
                for (int j = 0; j < 4; j++) acc[i][j] = 0.f;
        }
        __syncthreads();
    }

    const unsigned qb = lane & ~3u;
    const int liq = lane & 3;
    #pragma unroll
    for (int rowsel = 0; rowsel < 2; ++rowsel) {
        int mycnt = rowsel ? ch : cl;
        float s1 = rowsel ? s1_hi : s1_lo;
        float s2 = rowsel ? s2_hi : s2_lo;
        int   i1 = rowsel ? i1_hi : i1_lo;
        #pragma unroll
        for (int off = 1; off <= 2; off <<= 1) {
            float os1 = __shfl_xor_sync(0xFFFFFFFFu, s1, off);
            float os2 = __shfl_xor_sync(0xFFFFFFFFu, s2, off);
            int   oi1 = __shfl_xor_sync(0xFFFFFFFFu, i1, off);
            if (os1 > s1) { s2 = fmaxf(fmaxf(s1, os2), s2); s1 = os1; i1 = oi1; }
            else          { s2 = fmaxf(fmaxf(os1, os2), s2); }
        }
        bool skip = (s1 - s2) > SKIP_GAP;

        int l0 = __shfl_sync(0xFFFFFFFFu, mycnt, qb + 0);
        int l1 = __shfl_sync(0xFFFFFFFFu, mycnt, qb + 1);
        int l2 = __shfl_sync(0xFFFFFFFFu, mycnt, qb + 2);
        int l3 = __shfl_sync(0xFFFFFFFFu, mycnt, qb + 3);
        int m0 = min(l0, NLRING), m1 = min(l1, NLRING),
            m2 = min(l2, NLRING), m3 = min(l3, NLRING);
        int tot = m0 + m1 + m2 + m3;
        bool ovf = (l0 > NLRING) | (l1 > NLRING) | (l2 > NLRING) | (l3 > NLRING);
        int pre = (liq > 0 ? m0 : 0) + (liq > 1 ? m1 : 0) + (liq > 2 ? m2 : 0);
        int pix = n_base + wbase + (lane >> 2) + rowsel * 8;
        if (liq == 0) {
            if (skip) {
                g_cnt[pix] = 0;
                g_tok[pix] = i1;
                tok_out[pix] = (float)i1;
            } else {
                g_cnt[pix] = ovf ? 1000 : tot;
            }
        }
        if (!skip) {
            int myc = min(mycnt, NLRING);
            const unsigned short* rp = ringp + rowsel * NLRING;
            for (int i = 0; i < myc; ++i) g_cand[pix][pre + i] = rp[i];
        }
    }
}

// ---------------------------------------------------------------------------
// Rescore (R14): warp-per-candidate blocked, 4 in flight, early exit.
// ---------------------------------------------------------------------------
#define NCAND_BLK (32 * NC_MAX)

__global__ void __launch_bounds__(256) k_rescore(
    const float* __restrict__ cb, const float* __restrict__ z,
    float* __restrict__ tok_out)
{
    __shared__ float zs[32][260];
    __shared__ float zsq_s[32];
    __shared__ unsigned long long best_s[32];
    __shared__ int cnts[32], offs[33];
    __shared__ unsigned int asn[NCAND_BLK];
    const int t = threadIdx.x;
    const int wid = t >> 5, lane = t & 31;
    const int n_base = blockIdx.x * 32;
    const float* zsrc = z + (size_t)(n_base >> 8) * 65536 + (n_base & 255);

    if (t < 32) {
        best_s[t] = ~0ull;
        int c = g_cnt[n_base + t];
        if (c > NC_MAX) {
            int idx = atomicAdd(&g_nfb, 1);
            g_fblist[idx] = n_base + t;
            c = 0;
        }
        cnts[t] = c;
    }
    __syncthreads();
    if (t == 0) {
        int a = 0;
        #pragma unroll
        for (int i = 0; i < 32; i++) { offs[i] = a; a += cnts[i]; }
        offs[32] = a;
    }
    __syncthreads();
    const int T = offs[32];
    if (T == 0) return;

    for (int idx = t; idx < 8192; idx += 256) {
        int e = idx >> 5, p = idx & 31;
        zs[p][e] = zsrc[e * 256 + p];
    }
    __syncthreads();

    if (t < 32 && cnts[t] > 0) {
        const float* zr = zs[t];
        float s = 0.f;
        #pragma unroll 8
        for (int e = 0; e < 256; e++) { float v = zr[e]; s = fmaf(v, v, s); }
        zsq_s[t] = s;
    }
    __syncthreads();
    if (t < 32) {
        int o = offs[t], c = cnts[t];
        for (int i = 0; i < c; ++i)
            asn[o + i] = ((unsigned)t << 16) | g_cand[n_base + t][i];
    }
    __syncthreads();

    for (int base = wid; base < T; base += 32) {
        int idxs[4];
        float p[4];
        int pl[4], vv[4];
        #pragma unroll
        for (int u = 0; u < 4; u++) {
            int i = base + u * 8;
            idxs[u] = (i < T) ? i : base;
            unsigned a = asn[idxs[u]];
            pl[u] = a >> 16; vv[u] = a & 0xFFFF;
        }
        #pragma unroll
        for (int u = 0; u < 4; u++) {
            const float4* cp = reinterpret_cast<const float4*>(cb + (size_t)vv[u] * 256 + lane * 8);
            float4 c0 = cp[0], c1 = cp[1];
            const float* zr = zs[pl[u]] + lane * 8;
            float4 za = *reinterpret_cast<const float4*>(zr);
            float4 zb = *reinterpret_cast<const float4*>(zr + 4);
            float pp = za.x * c0.x;
            pp = fmaf(za.y, c0.y, pp);
            pp = fmaf(za.z, c0.z, pp);
            pp = fmaf(za.w, c0.w, pp);
            pp = fmaf(zb.x, c1.x, pp);
            pp = fmaf(zb.y, c1.y, pp);
            pp = fmaf(zb.z, c1.z, pp);
            pp = fmaf(zb.w, c1.w, pp);
            p[u] = pp;
        }
        #pragma unroll
        for (int o = 16; o; o >>= 1) {
            #pragma unroll
            for (int u = 0; u < 4; u++)
                p[u] += __shfl_xor_sync(0xFFFFFFFFu, p[u], o);
        }
        if (lane == 0) {
            #pragma unroll
            for (int u = 0; u < 4; u++) {
                if (base + u * 8 < T) {
                    float d = (zsq_s[pl[u]] + g_csq[vv[u]]) - 2.0f * p[u];
                    unsigned long long key =
                        ((unsigned long long)f2ord(d) << 32) | (unsigned int)vv[u];
                    atomicMin(&best_s[pl[u]], key);
                }
            }
        }
    }
    __syncthreads();

    if (t < 32 && cnts[t] > 0) {
        int pix = n_base + t;
        int tok = (int)(best_s[t] & 0xFFFFFFFFull);
        g_tok[pix] = tok;
        tok_out[pix] = (float)tok;
    }
}

// ---------------------------------------------------------------------------
// Fallback: block-per-pixel, warp-per-code (coalesced row reads).
// ---------------------------------------------------------------------------
__global__ void __launch_bounds__(256) k_fallback(
    const float* __restrict__ cb, const float* __restrict__ z,
    float* __restrict__ tok_out)
{
    __shared__ float zr[256];
    __shared__ float zsq_sh;
    __shared__ unsigned long long wmin[8];
    const int t = threadIdx.x;
    const int wid = t >> 5, lane = t & 31;
    const int n = g_nfb;

    for (int i = blockIdx.x; i < n; i += gridDim.x) {
        const int pix = g_fblist[i];
        const float* zsrc = z + (size_t)(pix >> 8) * 65536 + (pix & 255);
        zr[t] = zsrc[t * 256];
        __syncthreads();
        if (t == 0) {
            float s = 0.f;
            #pragma unroll 8
            for (int e = 0; e < 256; e++) { float v = zr[e]; s = fmaf(v, v, s); }
            zsq_sh = s;
        }
        __syncthreads();
        const float zq2 = zsq_sh;
        const float4 z0 = *reinterpret_cast<const float4*>(zr + lane * 8);
        const float4 z1 = *reinterpret_cast<const float4*>(zr + lane * 8 + 4);
        unsigned long long best = ~0ull;

        for (int v = wid * 512; v < wid * 512 + 512; v += 2) {
            const float4* c0p = reinterpret_cast<const float4*>(cb + (size_t)v * 256 + lane * 8);
            const float4* c1p = reinterpret_cast<const float4*>(cb + (size_t)(v + 1) * 256 + lane * 8);
            float4 c00 = c0p[0], c01 = c0p[1];
            float4 c10 = c1p[0], c11 = c1p[1];
            float p0 = z0.x * c00.x, p1 = z0.x * c10.x;
            p0 = fmaf(z0.y, c00.y, p0); p1 = fmaf(z0.y, c10.y, p1);
            p0 = fmaf(z0.z, c00.z, p0); p1 = fmaf(z0.z, c10.z, p1);
            p0 = fmaf(z0.w, c00.w, p0); p1 = fmaf(z0.w, c10.w, p1);
            p0 = fmaf(z1.x, c01.x, p0); p1 = fmaf(z1.x, c11.x, p1);
            p0 = fmaf(z1.y, c01.y, p0); p1 = fmaf(z1.y, c11.y, p1);
            p0 = fmaf(z1.z, c01.z, p0); p1 = fmaf(z1.z, c11.z, p1);
            p0 = fmaf(z1.w, c01.w, p0); p1 = fmaf(z1.w, c11.w, p1);
            #pragma unroll
            for (int o = 16; o; o >>= 1) {
                p0 += __shfl_xor_sync(0xFFFFFFFFu, p0, o);
                p1 += __shfl_xor_sync(0xFFFFFFFFu, p1, o);
            }
            float d0 = (zq2 + g_csq[v])     - 2.0f * p0;
            float d1 = (zq2 + g_csq[v + 1]) - 2.0f * p1;
            unsigned long long k0 = ((unsigned long long)f2ord(d0) << 32) | (unsigned int)v;
            unsigned long long k1 = ((unsigned long long)f2ord(d1) << 32) | (unsigned int)(v + 1);
            if (k0 < best) best = k0;
            if (k1 < best) best = k1;
        }
        if (lane == 0) wmin[wid] = best;
        __syncthreads();
        if (t == 0) {
            unsigned long long b = wmin[0];
            #pragma unroll
            for (int k = 1; k < 8; k++) if (wmin[k] < b) b = wmin[k];
            int tok = (int)(b & 0xFFFFFFFFull);
            g_tok[pix] = tok;
            tok_out[pix] = (float)tok;
        }
        __syncthreads();
    }
}

// ---------------------------------------------------------------------------
// Fused output gather: zq = cb[tok], recon = P[:, tok] + post_b.
// One block = one (img, channel) pair; hw = threadIdx.
// ---------------------------------------------------------------------------
__global__ void k_out(const float* __restrict__ cb, const float* __restrict__ post_b,
                      float* __restrict__ zq, float* __restrict__ recon)
{
    unsigned int g = blockIdx.x * 256 + threadIdx.x;
    int hw = g & 255, e = (g >> 8) & 255, img = g >> 16;
    int tok = g_tok[img * 256 + hw];
    zq[g] = cb[(size_t)tok * 256 + e];
    recon[g] = g_P[(size_t)e * 4096 + tok] + post_b[e];
}

// ---------------------------------------------------------------------------
extern "C" void kernel_launch(void* const* d_in, const int* in_sizes, int n_in,
                              void* d_out, int out_size) {
    const float* x      = (const float*)d_in[0];
    const float* cb     = (const float*)d_in[1];
    const float* pre_w  = (const float*)d_in[2];
    const float* pre_b  = (const float*)d_in[3];
    const float* post_w = (const float*)d_in[4];
    const float* post_b = (const float*)d_in[5];

    float* out   = (float*)d_out;
    float* zbuf  = out;
    float* zq    = out + 8388608;
    float* recon = out + 16777216;
    float* toks  = out + 25165824;

    static bool attr_done = false;
    if (!attr_done) {
        cudaFuncSetAttribute(k_dist_mma, cudaFuncAttributeMaxDynamicSharedMemorySize, SMEM_DIST);
        attr_done = true;
    }

    k_prep<<<VOCAB, 256>>>(cb);                                        // 1
    k_pgemm<<<dim3(32, 2), 256>>>(post_w, cb);                         // 2
    k_gemm256<true><<<dim3(2, 2, IMGS), 256>>>(pre_w, pre_b, x, zbuf); // 3
    k_dist_mma<<<NPIX / 128, 256, SMEM_DIST>>>(zbuf, toks);            // 4 (profiled slot)
    k_rescore<<<NPIX / 32, 256>>>(cb, zbuf, toks);                     // 5
    k_fallback<<<256, 256>>>(cb, zbuf, toks);                          // 6
    k_out<<<8388608 / 256, 256>>>(cb, post_b, zq, recon);              // 7
}

// round 17
// speedup vs baseline: 1.2354x; 1.0913x over previous
#include <cuda_runtime.h>
#include <cuda_bf16.h>
#include <cstdint>

#define IMGS   128
#define EMB    256
#define NPIX   32768
#define VOCAB  4096
#define NLRING 16
#define NC_MAX 64

__device__ float g_csq[VOCAB];
__device__ float g_csqh[VOCAB];
__device__ int   g_tok[NPIX];
__device__ __nv_bfloat16 g_cbh[VOCAB * EMB];
__device__ unsigned short g_cand[NPIX][NC_MAX];
__device__ int   g_cnt[NPIX];
__device__ int   g_nfb;
__device__ int   g_fblist[NPIX];
__device__ float g_P[EMB * VOCAB];

__device__ __forceinline__ unsigned int f2ord(float f) {
    unsigned int u = __float_as_uint(f);
    return (u & 0x80000000u) ? ~u : (u | 0x80000000u);
}
__device__ __forceinline__ uint32_t smem_u32(const void* p) {
    uint32_t a;
    asm("{ .reg .u64 t; cvta.to.shared.u64 t, %1; cvt.u32.u64 %0, t; }" : "=r"(a) : "l"(p));
    return a;
}

#define LDM4(r0, r1, r2, r3, addr)                                              \
    asm volatile("ldmatrix.sync.aligned.m8n8.x4.shared.b16 {%0,%1,%2,%3}, [%4];"\
        : "=r"(r0), "=r"(r1), "=r"(r2), "=r"(r3) : "r"(addr))

#define LDM4T(r0, r1, r2, r3, addr)                                             \
    asm volatile("ldmatrix.sync.aligned.m8n8.x4.trans.shared.b16 {%0,%1,%2,%3}, [%4];"\
        : "=r"(r0), "=r"(r1), "=r"(r2), "=r"(r3) : "r"(addr))

#define MMA16816(d, a0, a1, a2, a3, b0, b1)                                     \
    asm volatile("mma.sync.aligned.m16n8k16.row.col.f32.bf16.bf16.f32 "         \
        "{%0,%1,%2,%3},{%4,%5,%6,%7},{%8,%9},{%0,%1,%2,%3};"                    \
        : "+f"((d)[0]), "+f"((d)[1]), "+f"((d)[2]), "+f"((d)[3])                \
        : "r"(a0), "r"(a1), "r"(a2), "r"(a3), "r"(b0), "r"(b1))

#define CPA16(dst, src)                                                         \
    asm volatile("cp.async.cg.shared.global [%0], [%1], 16;" :: "r"(dst), "l"(src))
#define CP_COMMIT() asm volatile("cp.async.commit_group;" ::: "memory")

#define STS64(addr, u0, u1)                                                     \
    asm volatile("st.shared.v2.b32 [%0], {%1, %2};" :: "r"(addr), "r"(u0), "r"(u1) : "memory")

__device__ __forceinline__ void split2(float v0, float v1, uint32_t& hi, uint32_t& lo) {
    __nv_bfloat16 h0 = __float2bfloat16(v0), h1 = __float2bfloat16(v1);
    float l0 = v0 - __bfloat162float(h0);
    float l1 = v1 - __bfloat162float(h1);
    __nv_bfloat16 g0 = __float2bfloat16(l0), g1 = __float2bfloat16(l1);
    hi = ((uint32_t)__bfloat16_as_ushort(h1) << 16) | (uint32_t)__bfloat16_as_ushort(h0);
    lo = ((uint32_t)__bfloat16_as_ushort(g1) << 16) | (uint32_t)__bfloat16_as_ushort(g0);
}

// ---------------------------------------------------------------------------
__global__ void k_cbh(const float* __restrict__ cb) {
    int i = blockIdx.x * 256 + threadIdx.x;
    g_cbh[i] = __float2bfloat16(cb[i]);
}

__global__ void k_csq(const float* __restrict__ cb) {
    int t = threadIdx.x;
    if (blockIdx.x == 0 && t == 0) g_nfb = 0;
    int r = blockIdx.x * 4 + (t >> 5);
    int lane = t & 31;
    if (r < VOCAB) {
        const float* row = cb + r * EMB;
        float s = 0.f;
        #pragma unroll 4
        for (int e = lane; e < EMB; e += 32) { float v = row[e]; s += v * v; }
        #pragma unroll
        for (int o = 16; o; o >>= 1) s += __shfl_down_sync(0xFFFFFFFFu, s, o);
        if (lane == 0) { g_csq[r] = s; g_csqh[r] = 0.5f * s; }
    }
}

// ---------------------------------------------------------------------------
// P = post_w @ cb^T (fp32, 128x128 tile)
// ---------------------------------------------------------------------------
__global__ void __launch_bounds__(256) k_pgemm(
    const float* __restrict__ W, const float* __restrict__ cb)
{
    __shared__ float Ws[8][132];
    __shared__ float Cs[8][132];
    const int m0 = blockIdx.y * 128, v0 = blockIdx.x * 128;
    const int t = threadIdx.x;
    const int ty = t >> 4, tx = t & 15;

    float acc[8][8] = {};

    for (int e0 = 0; e0 < 256; e0 += 8) {
        {
            int m = t >> 1, e4 = (t & 1) * 4;
            float4 w4 = *reinterpret_cast<const float4*>(&W[(m0 + m) * 256 + e0 + e4]);
            Ws[e4 + 0][m] = w4.x; Ws[e4 + 1][m] = w4.y;
            Ws[e4 + 2][m] = w4.z; Ws[e4 + 3][m] = w4.w;
        }
        {
            int v = t >> 1, e4 = (t & 1) * 4;
            float4 c4 = *reinterpret_cast<const float4*>(&cb[(v0 + v) * 256 + e0 + e4]);
            Cs[e4 + 0][v] = c4.x; Cs[e4 + 1][v] = c4.y;
            Cs[e4 + 2][v] = c4.z; Cs[e4 + 3][v] = c4.w;
        }
        __syncthreads();
        #pragma unroll
        for (int k = 0; k < 8; k++) {
            float a[8], b[8];
            *reinterpret_cast<float4*>(a)     = *reinterpret_cast<float4*>(&Ws[k][ty * 8]);
            *reinterpret_cast<float4*>(a + 4) = *reinterpret_cast<float4*>(&Ws[k][ty * 8 + 4]);
            *reinterpret_cast<float4*>(b)     = *reinterpret_cast<float4*>(&Cs[k][tx * 8]);
            *reinterpret_cast<float4*>(b + 4) = *reinterpret_cast<float4*>(&Cs[k][tx * 8 + 4]);
            #pragma unroll
            for (int i = 0; i < 8; i++)
                #pragma unroll
                for (int j = 0; j < 8; j++)
                    acc[i][j] += a[i] * b[j];
        }
        __syncthreads();
    }

    #pragma unroll
    for (int i = 0; i < 8; i++) {
        float* dst = g_P + (size_t)(m0 + ty * 8 + i) * 4096 + v0 + tx * 8;
        *reinterpret_cast<float4*>(dst)     = *reinterpret_cast<float4*>(&acc[i][0]);
        *reinterpret_cast<float4*>(dst + 4) = *reinterpret_cast<float4*>(&acc[i][4]);
    }
}

// ---------------------------------------------------------------------------
// Pre-GEMM via split-bf16 tensor cores: Z = W @ (2X-1), 3-mma hi/lo scheme.
// CTA: 128 m x 64 n, K chunks of 64, double-buffered smem stages of 48KB.
// grid (4 n-tiles, 2 m-tiles, 128 imgs).
// Stage layout: AH 16K | AL 16K | BH 8K | BL 8K   (128B swizzled rows)
// ---------------------------------------------------------------------------
#define GAH 0
#define GAL 16384
#define GBH 32768
#define GBL 40960
#define GSTRIDE 49152
#define SMEM_GTC 98304

__global__ void __launch_bounds__(256) k_gemm_tc(
    const float* __restrict__ W, const float* __restrict__ bias,
    const float* __restrict__ X, float* __restrict__ Out)
{
    extern __shared__ char smem[];
    const uint32_t sb = smem_u32(smem);
    const int t = threadIdx.x;
    const int wid = t >> 5, lane = t & 31;
    const int gn0 = blockIdx.x * 64;
    const int gm0 = blockIdx.y * 128;
    const int img = blockIdx.z;
    const float* in = X + (size_t)img * 65536;
    float* out = Out + (size_t)img * 65536;

    const int wbase = wid * 16;
    const int arow_l = (lane & 7) + ((lane >> 3) & 1) * 8;  // 0..15
    const int arow = wbase + arow_l;
    const int ahalf = lane >> 4;
    const int bk_off = ((lane >> 3) & 1) * 8 + (lane & 7);

    float acc[8][4];
    #pragma unroll
    for (int i = 0; i < 8; i++)
        #pragma unroll
        for (int j = 0; j < 4; j++) acc[i][j] = 0.f;

    #pragma unroll 1
    for (int c = 0; c < 4; ++c) {
        const uint32_t stg = sb + (uint32_t)(c & 1) * GSTRIDE;
        // ---- A: W[gm0..+127][c*64..+63] -> hi/lo swizzled ----
        {
            const int m = t >> 1;
            const int kb = (t & 1) * 32;
            const float* src = W + (size_t)(gm0 + m) * 256 + c * 64 + kb;
            const uint32_t rowH = stg + GAH + (uint32_t)m * 128;
            const uint32_t rowL = stg + GAL + (uint32_t)m * 128;
            const uint32_t msw = (uint32_t)(m & 7);
            #pragma unroll
            for (int j = 0; j < 32; j += 4) {
                float4 v = *reinterpret_cast<const float4*>(src + j);
                uint32_t h0, l0, h1, l1;
                split2(v.x, v.y, h0, l0);
                split2(v.z, v.w, h1, l1);
                int k0 = kb + j;
                uint32_t su = (((uint32_t)(k0 >> 3)) ^ msw) << 4;
                uint32_t off = (uint32_t)(k0 & 7) * 2;
                STS64(rowH + su + off, h0, h1);
                STS64(rowL + su + off, l0, l1);
            }
        }
        // ---- B: X[c*64..+63][gn0..+63], xform 2x-1 -> hi/lo swizzled ----
        {
            #pragma unroll
            for (int i = 0; i < 4; i++) {
                int f4 = i * 256 + t;
                int k = f4 >> 4;
                int n4 = (f4 & 15) * 4;
                float4 v = *reinterpret_cast<const float4*>(in + (size_t)(c * 64 + k) * 256 + gn0 + n4);
                v.x = 2.f * v.x - 1.f; v.y = 2.f * v.y - 1.f;
                v.z = 2.f * v.z - 1.f; v.w = 2.f * v.w - 1.f;
                uint32_t h0, l0, h1, l1;
                split2(v.x, v.y, h0, l0);
                split2(v.z, v.w, h1, l1);
                uint32_t su = (((uint32_t)(n4 >> 3)) ^ (uint32_t)(k & 7)) << 4;
                uint32_t off = (uint32_t)(n4 & 7) * 2;
                uint32_t baseH = stg + GBH + (uint32_t)k * 128 + su + off;
                uint32_t baseL = stg + GBL + (uint32_t)k * 128 + su + off;
                STS64(baseH, h0, h1);
                STS64(baseL, l0, l1);
            }
        }
        __syncthreads();

        // ---- MMA over 4 k16 steps ----
        const uint32_t abH = stg + GAH + (uint32_t)arow * 128;
        const uint32_t abL = stg + GAL + (uint32_t)arow * 128;
        #pragma unroll
        for (int ks = 0; ks < 4; ks++) {
            uint32_t ah0, ah1, ah2, ah3, al0, al1, al2, al3;
            {
                uint32_t su = (((uint32_t)(2 * ks + ahalf)) ^ (uint32_t)(arow & 7)) << 4;
                LDM4(ah0, ah1, ah2, ah3, abH + su);
                LDM4(al0, al1, al2, al3, abL + su);
            }
            const int bk = ks * 16 + bk_off;
            const uint32_t bbH = stg + GBH + (uint32_t)bk * 128;
            const uint32_t bbL = stg + GBL + (uint32_t)bk * 128;
            const uint32_t bsw = (uint32_t)(bk & 7);
            #pragma unroll
            for (int g = 0; g < 4; g++) {
                uint32_t su = (((uint32_t)(2 * g + ahalf)) ^ bsw) << 4;
                uint32_t bh0, bh1, bh2, bh3, bl0, bl1, bl2, bl3;
                LDM4T(bh0, bh1, bh2, bh3, bbH + su);
                LDM4T(bl0, bl1, bl2, bl3, bbL + su);
                MMA16816(acc[2 * g],     ah0, ah1, ah2, ah3, bh0, bh1);
                MMA16816(acc[2 * g],     ah0, ah1, ah2, ah3, bl0, bl1);
                MMA16816(acc[2 * g],     al0, al1, al2, al3, bh0, bh1);
                MMA16816(acc[2 * g + 1], ah0, ah1, ah2, ah3, bh2, bh3);
                MMA16816(acc[2 * g + 1], ah0, ah1, ah2, ah3, bl2, bl3);
                MMA16816(acc[2 * g + 1], al0, al1, al2, al3, bh2, bh3);
            }
        }
    }

    // ---- epilogue: add bias, write z[m][n] ----
    const int mr = gm0 + wbase + (lane >> 2);
    const int nc = gn0 + 2 * (lane & 3);
    const float b0 = bias[mr];
    const float b8 = bias[mr + 8];
    #pragma unroll
    for (int nf = 0; nf < 8; nf++) {
        float2 w0 = make_float2(acc[nf][0] + b0, acc[nf][1] + b0);
        float2 w1 = make_float2(acc[nf][2] + b8, acc[nf][3] + b8);
        *reinterpret_cast<float2*>(out + (size_t)mr * 256 + nc + nf * 8) = w0;
        *reinterpret_cast<float2*>(out + (size_t)(mr + 8) * 256 + nc + nf * 8) = w1;
    }
}

// ---------------------------------------------------------------------------
// bf16 mma.sync score GEMM, gated prune + group top-2 skip (R14/R16).
// ---------------------------------------------------------------------------
#define AOFF      0
#define B0OFF     65536
#define B1OFF     81920
#define CSQOFF    98304
#define RINGOFF   98560
#define SMEM_DIST 114944
#define MARGIN    2.5e-5f
#define SKIP_GAP  2.5e-5f

__global__ void __launch_bounds__(256, 2) k_dist_mma(
    const float* __restrict__ z, float* __restrict__ tok_out)
{
    extern __shared__ char smem[];
    const uint32_t sb = smem_u32(smem);
    const int t = threadIdx.x;
    const int wid = t >> 5, lane = t & 31;
    const int n_base = blockIdx.x * 128;

    {
        const float* zsrc = z + (size_t)(n_base >> 8) * 65536 + (n_base & 255);
        float* scr = reinterpret_cast<float*>(smem + B0OFF);
        for (int kb = 0; kb < 8; kb++) {
            int e_l = t >> 3;
            int pg = (t & 7) * 16;
            const float4* s4 = reinterpret_cast<const float4*>(zsrc + (kb * 32 + e_l) * 256 + pg);
            float4 v0 = s4[0], v1 = s4[1], v2 = s4[2], v3 = s4[3];
            float4* d4 = reinterpret_cast<float4*>(scr + e_l * 128 + pg);
            d4[0] = v0; d4[1] = v1; d4[2] = v2; d4[3] = v3;
            __syncthreads();
            int pix = t & 127, half = t >> 7;
            #pragma unroll
            for (int jj = 0; jj < 8; jj++) {
                int el0 = (half * 8 + jj) * 2;
                float a = scr[el0 * 128 + pix], b = scr[(el0 + 1) * 128 + pix];
                uint32_t u;
                asm("cvt.rn.bf16x2.f32 %0, %1, %2;" : "=r"(u) : "f"(b), "f"(a));
                int eg = kb * 32 + el0;
                uint32_t unit = (uint32_t)(eg >> 3);
                uint32_t su = (unit & 24) | ((unit ^ (uint32_t)(pix & 7)) & 7);
                uint32_t addr = sb + AOFF + (uint32_t)pix * 512 + su * 16 + (eg & 7) * 2;
                asm volatile("st.shared.b32 [%0], %1;" :: "r"(addr), "r"(u) : "memory");
            }
            __syncthreads();
        }
    }

    const int wbase = wid * 16;
    const int arow = wbase + (lane & 7) + ((lane >> 3) & 1) * 8;
    const uint32_t aswz = (uint32_t)(arow & 7);
    const uint32_t abase = sb + AOFF + (uint32_t)arow * 512;
    const int ag2 = lane >> 4;
    const int brp = ((lane >> 4) & 1) * 8 + (lane & 7);
    const int bg1 = (lane >> 3) & 1;
    float* csq_s = reinterpret_cast<float*>(smem + CSQOFF);
    unsigned short* ringp =
        reinterpret_cast<unsigned short*>(smem + RINGOFF) + (wid * 32 + lane) * (2 * NLRING);

    float acc[8][4];
    #pragma unroll
    for (int i = 0; i < 8; i++)
        #pragma unroll
        for (int j = 0; j < 4; j++) acc[i][j] = 0.f;

    float rmx_lo = -1e30f, rmx_hi = -1e30f;
    float s1_lo = -1e30f, s2_lo = -1e30f;
    float s1_hi = -1e30f, s2_hi = -1e30f;
    int   i1_lo = 0, i1_hi = 0;
    int cl = 0, ch = 0;

    auto loadB = [&](int nt, int kc, uint32_t boff) {
        int code = t >> 2;
        const char* src = reinterpret_cast<const char*>(
            g_cbh + ((size_t)(nt * 64 + code)) * 256 + kc * 128 + (t & 3) * 32);
        uint32_t drow = sb + boff + (uint32_t)code * 256;
        uint32_t sw = (uint32_t)(code & 7);
        #pragma unroll
        for (int i = 0; i < 4; i++) {
            uint32_t u = (uint32_t)((t & 3) * 4 + i);
            uint32_t su = ((u ^ sw) & 7) | (u & 8);
            CPA16(drow + su * 16, src + i * 16);
        }
    };

    loadB(0, 0, B0OFF);
    CP_COMMIT();

    for (int c = 0; c < 128; ++c) {
        const int nt = c >> 1, kc = c & 1;
        if (c < 127) { loadB((c + 1) >> 1, (c + 1) & 1, ((c + 1) & 1) ? B1OFF : B0OFF); CP_COMMIT(); }
        if (kc == 0 && t < 64) csq_s[t] = g_csqh[nt * 64 + t];
        if (c < 127) asm volatile("cp.async.wait_group 1;" ::: "memory");
        else         asm volatile("cp.async.wait_group 0;" ::: "memory");
        __syncthreads();

        const uint32_t bbuf = sb + ((c & 1) ? B1OFF : B0OFF);
        #pragma unroll
        for (int ks = 0; ks < 8; ks++) {
            uint32_t a0, a1, a2, a3;
            {
                uint32_t unit = (uint32_t)(kc * 16 + 2 * ks + ag2);
                uint32_t su = (unit & 24) | ((unit ^ aswz) & 7);
                LDM4(a0, a1, a2, a3, abase + su * 16);
            }
            #pragma unroll
            for (int p = 0; p < 4; p++) {
                int brow = p * 16 + brp;
                uint32_t unit = (uint32_t)(2 * ks + bg1);
                uint32_t su = (unit & 8) | ((unit ^ (uint32_t)(brow & 7)) & 7);
                uint32_t b0, b1, b2, b3;
                LDM4(b0, b1, b2, b3, bbuf + (uint32_t)brow * 256 + su * 16);
                MMA16816(acc[2 * p],     a0, a1, a2, a3, b0, b1);
                MMA16816(acc[2 * p + 1], a0, a1, a2, a3, b2, b3);
            }
        }

        if (kc == 1) {
            const int vtile = nt * 64;
            #pragma unroll
            for (int q = 0; q < 4; ++q) {
                const int cbase = q * 16 + 2 * (lane & 3);
                float2 cq0 = *reinterpret_cast<const float2*>(csq_s + cbase);
                float2 cq1 = *reinterpret_cast<const float2*>(csq_s + cbase + 8);
                const int nf0 = 2 * q, nf1 = 2 * q + 1;
                {
                    float s0 = acc[nf0][0] - cq0.x, s1v = acc[nf0][1] - cq0.y;
                    float s2v = acc[nf1][0] - cq1.x, s3v = acc[nf1][1] - cq1.y;
                    float m01 = fmaxf(s0, s1v), m23 = fmaxf(s2v, s3v);
                    float m = fmaxf(m01, m23);
                    if (m > s1_lo) {
                        float mn01 = fminf(s0, s1v), mn23 = fminf(s2v, s3v);
                        float sec = (m01 >= m23) ? fmaxf(m23, mn01) : fmaxf(m01, mn23);
                        int gi = (m == s0) ? cbase : (m == s1v) ? (cbase + 1)
                               : (m == s2v) ? (cbase + 8) : (cbase + 9);
                        s2_lo = fmaxf(s1_lo, sec);
                        s1_lo = m;
                        i1_lo = vtile + gi;
                    } else {
                        s2_lo = fmaxf(s2_lo, m);
                    }
                    float base = fmaxf(rmx_lo, s1_lo) - MARGIN;
                    if (m > base) {
                        if (s0  > base) { if (cl < NLRING) ringp[cl] = (unsigned short)(vtile + cbase);     cl++; }
                        if (s1v > base) { if (cl < NLRING) ringp[cl] = (unsigned short)(vtile + cbase + 1); cl++; }
                        if (s2v > base) { if (cl < NLRING) ringp[cl] = (unsigned short)(vtile + cbase + 8); cl++; }
                        if (s3v > base) { if (cl < NLRING) ringp[cl] = (unsigned short)(vtile + cbase + 9); cl++; }
                    }
                }
                {
                    float s0 = acc[nf0][2] - cq0.x, s1v = acc[nf0][3] - cq0.y;
                    float s2v = acc[nf1][2] - cq1.x, s3v = acc[nf1][3] - cq1.y;
                    float m01 = fmaxf(s0, s1v), m23 = fmaxf(s2v, s3v);
                    float m = fmaxf(m01, m23);
                    if (m > s1_hi) {
                        float mn01 = fminf(s0, s1v), mn23 = fminf(s2v, s3v);
                        float sec = (m01 >= m23) ? fmaxf(m23, mn01) : fmaxf(m01, mn23);
                        int gi = (m == s0) ? cbase : (m == s1v) ? (cbase + 1)
                               : (m == s2v) ? (cbase + 8) : (cbase + 9);
                        s2_hi = fmaxf(s1_hi, sec);
                        s1_hi = m;
                        i1_hi = vtile + gi;
                    } else {
                        s2_hi = fmaxf(s2_hi, m);
                    }
                    float base = fmaxf(rmx_hi, s1_hi) - MARGIN;
                    if (m > base) {
                        if (s0  > base) { if (ch < NLRING) ringp[NLRING + ch] = (unsigned short)(vtile + cbase);     ch++; }
                        if (s1v > base) { if (ch < NLRING) ringp[NLRING + ch] = (unsigned short)(vtile + cbase + 1); ch++; }
                        if (s2v > base) { if (ch < NLRING) ringp[NLRING + ch] = (unsigned short)(vtile + cbase + 8); ch++; }
                        if (s3v > base) { if (ch < NLRING) ringp[NLRING + ch] = (unsigned short)(vtile + cbase + 9); ch++; }
                    }
                }
            }
            {
                float q0 = fmaxf(s1_lo, __shfl_xor_sync(0xFFFFFFFFu, s1_lo, 1));
                rmx_lo = fmaxf(q0, __shfl_xor_sync(0xFFFFFFFFu, q0, 2));
                float q1 = fmaxf(s1_hi, __shfl_xor_sync(0xFFFFFFFFu, s1_hi, 1));
                rmx_hi = fmaxf(q1, __shfl_xor_sync(0xFFFFFFFFu, q1, 2));
            }
            #pragma unroll
            for (int i = 0; i < 8; i++)
                #pragma unroll
                for (int j = 0; j < 4; j++) acc[i][j] = 0.f;
        }
        __syncthreads();
    }

    const unsigned qb = lane & ~3u;
    const int liq = lane & 3;
    #pragma unroll
    for (int rowsel = 0; rowsel < 2; ++rowsel) {
        int mycnt = rowsel ? ch : cl;
        float s1 = rowsel ? s1_hi : s1_lo;
        float s2 = rowsel ? s2_hi : s2_lo;
        int   i1 = rowsel ? i1_hi : i1_lo;
        #pragma unroll
        for (int off = 1; off <= 2; off <<= 1) {
            float os1 = __shfl_xor_sync(0xFFFFFFFFu, s1, off);
            float os2 = __shfl_xor_sync(0xFFFFFFFFu, s2, off);
            int   oi1 = __shfl_xor_sync(0xFFFFFFFFu, i1, off);
            if (os1 > s1) { s2 = fmaxf(fmaxf(s1, os2), s2); s1 = os1; i1 = oi1; }
            else          { s2 = fmaxf(fmaxf(os1, os2), s2); }
        }
        bool skip = (s1 - s2) > SKIP_GAP;

        int l0 = __shfl_sync(0xFFFFFFFFu, mycnt, qb + 0);
        int l1 = __shfl_sync(0xFFFFFFFFu, mycnt, qb + 1);
        int l2 = __shfl_sync(0xFFFFFFFFu, mycnt, qb + 2);
        int l3 = __shfl_sync(0xFFFFFFFFu, mycnt, qb + 3);
        int m0 = min(l0, NLRING), m1 = min(l1, NLRING),
            m2 = min(l2, NLRING), m3 = min(l3, NLRING);
        int tot = m0 + m1 + m2 + m3;
        bool ovf = (l0 > NLRING) | (l1 > NLRING) | (l2 > NLRING) | (l3 > NLRING);
        int pre = (liq > 0 ? m0 : 0) + (liq > 1 ? m1 : 0) + (liq > 2 ? m2 : 0);
        int pix = n_base + wbase + (lane >> 2) + rowsel * 8;
        if (liq == 0) {
            if (skip) {
                g_cnt[pix] = 0;
                g_tok[pix] = i1;
                tok_out[pix] = (float)i1;
            } else {
                g_cnt[pix] = ovf ? 1000 : tot;
            }
        }
        if (!skip) {
            int myc = min(mycnt, NLRING);
            const unsigned short* rp = ringp + rowsel * NLRING;
            for (int i = 0; i < myc; ++i) g_cand[pix][pre + i] = rp[i];
        }
    }
}

// ---------------------------------------------------------------------------
// Rescore: warp-per-candidate blocked, 4 in flight, early exit.
// ---------------------------------------------------------------------------
#define NCAND_BLK (32 * NC_MAX)

__global__ void __launch_bounds__(256) k_rescore(
    const float* __restrict__ cb, const float* __restrict__ z,
    float* __restrict__ tok_out)
{
    __shared__ float zs[32][260];
    __shared__ float zsq_s[32];
    __shared__ unsigned long long best_s[32];
    __shared__ int cnts[32], offs[33];
    __shared__ unsigned int asn[NCAND_BLK];
    const int t = threadIdx.x;
    const int wid = t >> 5, lane = t & 31;
    const int n_base = blockIdx.x * 32;
    const float* zsrc = z + (size_t)(n_base >> 8) * 65536 + (n_base & 255);

    if (t < 32) {
        best_s[t] = ~0ull;
        int c = g_cnt[n_base + t];
        if (c > NC_MAX) {
            int idx = atomicAdd(&g_nfb, 1);
            g_fblist[idx] = n_base + t;
            c = 0;
        }
        cnts[t] = c;
    }
    __syncthreads();
    if (t == 0) {
        int a = 0;
        #pragma unroll
        for (int i = 0; i < 32; i++) { offs[i] = a; a += cnts[i]; }
        offs[32] = a;
    }
    __syncthreads();
    const int T = offs[32];
    if (T == 0) return;

    for (int idx = t; idx < 8192; idx += 256) {
        int e = idx >> 5, p = idx & 31;
        zs[p][e] = zsrc[e * 256 + p];
    }
    __syncthreads();

    if (t < 32 && cnts[t] > 0) {
        const float* zr = zs[t];
        float s = 0.f;
        #pragma unroll 8
        for (int e = 0; e < 256; e++) { float v = zr[e]; s = fmaf(v, v, s); }
        zsq_s[t] = s;
    }
    __syncthreads();
    if (t < 32) {
        int o = offs[t], c = cnts[t];
        for (int i = 0; i < c; ++i)
            asn[o + i] = ((unsigned)t << 16) | g_cand[n_base + t][i];
    }
    __syncthreads();

    for (int base = wid; base < T; base += 32) {
        int idxs[4];
        float p[4];
        int pl[4], vv[4];
        #pragma unroll
        for (int u = 0; u < 4; u++) {
            int i = base + u * 8;
            idxs[u] = (i < T) ? i : base;
            unsigned a = asn[idxs[u]];
            pl[u] = a >> 16; vv[u] = a & 0xFFFF;
        }
        #pragma unroll
        for (int u = 0; u < 4; u++) {
            const float4* cp = reinterpret_cast<const float4*>(cb + (size_t)vv[u] * 256 + lane * 8);
            float4 c0 = cp[0], c1 = cp[1];
            const float* zr = zs[pl[u]] + lane * 8;
            float4 za = *reinterpret_cast<const float4*>(zr);
            float4 zb = *reinterpret_cast<const float4*>(zr + 4);
            float pp = za.x * c0.x;
            pp = fmaf(za.y, c0.y, pp);
            pp = fmaf(za.z, c0.z, pp);
            pp = fmaf(za.w, c0.w, pp);
            pp = fmaf(zb.x, c1.x, pp);
            pp = fmaf(zb.y, c1.y, pp);
            pp = fmaf(zb.z, c1.z, pp);
            pp = fmaf(zb.w, c1.w, pp);
            p[u] = pp;
        }
        #pragma unroll
        for (int o = 16; o; o >>= 1) {
            #pragma unroll
            for (int u = 0; u < 4; u++)
                p[u] += __shfl_xor_sync(0xFFFFFFFFu, p[u], o);
        }
        if (lane == 0) {
            #pragma unroll
            for (int u = 0; u < 4; u++) {
                if (base + u * 8 < T) {
                    float d = (zsq_s[pl[u]] + g_csq[vv[u]]) - 2.0f * p[u];
                    unsigned long long key =
                        ((unsigned long long)f2ord(d) << 32) | (unsigned int)vv[u];
                    atomicMin(&best_s[pl[u]], key);
                }
            }
        }
    }
    __syncthreads();

    if (t < 32 && cnts[t] > 0) {
        int pix = n_base + t;
        int tok = (int)(best_s[t] & 0xFFFFFFFFull);
        g_tok[pix] = tok;
        tok_out[pix] = (float)tok;
    }
}

// ---------------------------------------------------------------------------
// Fallback: block-per-pixel, warp-per-code (coalesced row reads).
// ---------------------------------------------------------------------------
__global__ void __launch_bounds__(256) k_fallback(
    const float* __restrict__ cb, const float* __restrict__ z,
    float* __restrict__ tok_out)
{
    __shared__ float zr[256];
    __shared__ float zsq_sh;
    __shared__ unsigned long long wmin[8];
    const int t = threadIdx.x;
    const int wid = t >> 5, lane = t & 31;
    const int n = g_nfb;

    for (int i = blockIdx.x; i < n; i += gridDim.x) {
        const int pix = g_fblist[i];
        const float* zsrc = z + (size_t)(pix >> 8) * 65536 + (pix & 255);
        zr[t] = zsrc[t * 256];
        __syncthreads();
        if (t == 0) {
            float s = 0.f;
            #pragma unroll 8
            for (int e = 0; e < 256; e++) { float v = zr[e]; s = fmaf(v, v, s); }
            zsq_sh = s;
        }
        __syncthreads();
        const float zq2 = zsq_sh;
        const float4 z0 = *reinterpret_cast<const float4*>(zr + lane * 8);
        const float4 z1 = *reinterpret_cast<const float4*>(zr + lane * 8 + 4);
        unsigned long long best = ~0ull;

        for (int v = wid * 512; v < wid * 512 + 512; v += 2) {
            const float4* c0p = reinterpret_cast<const float4*>(cb + (size_t)v * 256 + lane * 8);
            const float4* c1p = reinterpret_cast<const float4*>(cb + (size_t)(v + 1) * 256 + lane * 8);
            float4 c00 = c0p[0], c01 = c0p[1];
            float4 c10 = c1p[0], c11 = c1p[1];
            float p0 = z0.x * c00.x, p1 = z0.x * c10.x;
            p0 = fmaf(z0.y, c00.y, p0); p1 = fmaf(z0.y, c10.y, p1);
            p0 = fmaf(z0.z, c00.z, p0); p1 = fmaf(z0.z, c10.z, p1);
            p0 = fmaf(z0.w, c00.w, p0); p1 = fmaf(z0.w, c10.w, p1);
            p0 = fmaf(z1.x, c01.x, p0); p1 = fmaf(z1.x, c11.x, p1);
            p0 = fmaf(z1.y, c01.y, p0); p1 = fmaf(z1.y, c11.y, p1);
            p0 = fmaf(z1.z, c01.z, p0); p1 = fmaf(z1.z, c11.z, p1);
            p0 = fmaf(z1.w, c01.w, p0); p1 = fmaf(z1.w, c11.w, p1);
            #pragma unroll
            for (int o = 16; o; o >>= 1) {
                p0 += __shfl_xor_sync(0xFFFFFFFFu, p0, o);
                p1 += __shfl_xor_sync(0xFFFFFFFFu, p1, o);
            }
            float d0 = (zq2 + g_csq[v])     - 2.0f * p0;
            float d1 = (zq2 + g_csq[v + 1]) - 2.0f * p1;
            unsigned long long k0 = ((unsigned long long)f2ord(d0) << 32) | (unsigned int)v;
            unsigned long long k1 = ((unsigned long long)f2ord(d1) << 32) | (unsigned int)(v + 1);
            if (k0 < best) best = k0;
            if (k1 < best) best = k1;
        }
        if (lane == 0) wmin[wid] = best;
        __syncthreads();
        if (t == 0) {
            unsigned long long b = wmin[0];
            #pragma unroll
            for (int k = 1; k < 8; k++) if (wmin[k] < b) b = wmin[k];
            int tok = (int)(b & 0xFFFFFFFFull);
            g_tok[pix] = tok;
            tok_out[pix] = (float)tok;
        }
        __syncthreads();
    }
}

// ---------------------------------------------------------------------------
// Fused output gather: zq = cb[tok], recon = P[:, tok] + post_b.
// ---------------------------------------------------------------------------
__global__ void k_out(const float* __restrict__ cb, const float* __restrict__ post_b,
                      float* __restrict__ zq, float* __restrict__ recon)
{
    unsigned int g = blockIdx.x * 256 + threadIdx.x;
    int hw = g & 255, e = (g >> 8) & 255, img = g >> 16;
    int tok = g_tok[img * 256 + hw];
    zq[g] = cb[(size_t)tok * 256 + e];
    recon[g] = g_P[(size_t)e * 4096 + tok] + post_b[e];
}

// ---------------------------------------------------------------------------
extern "C" void kernel_launch(void* const* d_in, const int* in_sizes, int n_in,
                              void* d_out, int out_size) {
    const float* x      = (const float*)d_in[0];
    const float* cb     = (const float*)d_in[1];
    const float* pre_w  = (const float*)d_in[2];
    const float* pre_b  = (const float*)d_in[3];
    const float* post_w = (const float*)d_in[4];
    const float* post_b = (const float*)d_in[5];

    float* out   = (float*)d_out;
    float* zbuf  = out;
    float* zq    = out + 8388608;
    float* recon = out + 16777216;
    float* toks  = out + 25165824;

    static bool attr_done = false;
    if (!attr_done) {
        cudaFuncSetAttribute(k_dist_mma, cudaFuncAttributeMaxDynamicSharedMemorySize, SMEM_DIST);
        cudaFuncSetAttribute(k_gemm_tc,  cudaFuncAttributeMaxDynamicSharedMemorySize, SMEM_GTC);
        attr_done = true;
    }

    k_cbh<<<4096, 256>>>(cb);                                              // 1
    k_csq<<<1024, 128>>>(cb);                                              // 2
    k_pgemm<<<dim3(32, 2), 256>>>(post_w, cb);                             // 3
    k_gemm_tc<<<dim3(4, 2, IMGS), 256, SMEM_GTC>>>(pre_w, pre_b, x, zbuf); // 4 (profiled)
    k_dist_mma<<<NPIX / 128, 256, SMEM_DIST>>>(zbuf, toks);                // 5
    k_rescore<<<NPIX / 32, 256>>>(cb, zbuf, toks);                         // 6
    k_fallback<<<256, 256>>>(cb, zbuf, toks);                              // 7
    k_out<<<8388608 / 256, 256>>>(cb, post_b, zq, recon);                  // 8
}